// round 11
// baseline (speedup 1.0000x reference)
#include <cuda_runtime.h>
#include <cuda_bf16.h>
#include <cstdint>

#define Bb 4
#define Tt 2048
#define Ee 512
#define KBLK 64
#define NBLK 32
#define MROWS (Bb * Tt)        // 8192
#define NQKV (3 * Ee)          // 1536
#define ESPL 4

// ---------------- scratch (__device__ globals) ------------------------------
__device__ __nv_bfloat16 g_xhi[MROWS * Ee];
__device__ __nv_bfloat16 g_xlo[MROWS * Ee];
__device__ __nv_bfloat16 g_Whi[NQKV * Ee];
__device__ __nv_bfloat16 g_Wlo[NQKV * Ee];
__device__ __nv_bfloat16 g_Uhi[Ee * Ee];           // Wu1 (cols 0..511) split hi
__device__ __nv_bfloat16 g_Ulo[Ee * Ee];
__device__ __nv_bfloat16 g_chi[MROWS * Ee];        // comb = h1 only (512 wide)
__device__ __nv_bfloat16 g_clo[MROWS * Ee];
__device__ __nv_bfloat16 g_kqh[MROWS * 1024];      // K|Q bf16 hi (stride 1024)
__device__ __nv_bfloat16 g_kql[MROWS * 1024];      // K|Q bf16 lo
__device__ float g_V[MROWS * Ee];                  // V fp32 (stride 512)
__device__ float g_bias[NQKV];
__device__ float g_S1[Bb * NBLK * 64 * 64];        // 2 MB
__device__ float g_S2[Bb * NBLK * 64 * 32];        // 1 MB
__device__ float g_M2[Bb * 32 * Ee];               // V_starts @ Wu2^T

// ---------------- PTX helpers ----------------------------------------------
__device__ __forceinline__ uint32_t smem_u32(const void* p) {
    uint32_t a;
    asm("{ .reg .u64 t; cvta.to.shared.u64 t, %1; cvt.u32.u64 %0, t; }"
        : "=r"(a) : "l"(p));
    return a;
}
#define CP_ASYNC16(dst, src) \
    asm volatile("cp.async.cg.shared.global [%0], [%1], 16;" :: "r"(dst), "l"(src))
#define CP_COMMIT() asm volatile("cp.async.commit_group;" ::: "memory")
#define CP_WAIT1()  asm volatile("cp.async.wait_group 1;" ::: "memory")
#define CP_WAIT0()  asm volatile("cp.async.wait_group 0;" ::: "memory")

__device__ __forceinline__ void ldm_x4(uint32_t* r, uint32_t addr) {
    asm volatile("ldmatrix.sync.aligned.m8n8.x4.shared.b16 {%0,%1,%2,%3}, [%4];"
                 : "=r"(r[0]), "=r"(r[1]), "=r"(r[2]), "=r"(r[3]) : "r"(addr));
}
__device__ __forceinline__ void mma16816(float* c, const uint32_t* a, const uint32_t* b) {
    asm volatile("mma.sync.aligned.m16n8k16.row.col.f32.bf16.bf16.f32 "
                 "{%0,%1,%2,%3}, {%4,%5,%6,%7}, {%8,%9}, {%0,%1,%2,%3};"
                 : "+f"(c[0]), "+f"(c[1]), "+f"(c[2]), "+f"(c[3])
                 : "r"(a[0]), "r"(a[1]), "r"(a[2]), "r"(a[3]), "r"(b[0]), "r"(b[1]));
}

__device__ __forceinline__ void split_pair_store(
    float x, float y, __nv_bfloat16* hi, __nv_bfloat16* lo, size_t off)
{
    __nv_bfloat16 h0 = __float2bfloat16(x);
    __nv_bfloat16 h1 = __float2bfloat16(y);
    __nv_bfloat16 l0 = __float2bfloat16(x - __bfloat162float(h0));
    __nv_bfloat16 l1 = __float2bfloat16(y - __bfloat162float(h1));
    __nv_bfloat162 hh; hh.x = h0; hh.y = h1;
    __nv_bfloat162 ll; ll.x = l0; ll.y = l1;
    *(__nv_bfloat162*)(hi + off) = hh;
    *(__nv_bfloat162*)(lo + off) = ll;
}

// ---------------- split-bf16 NT GEMM (BK=32, 2-stage, 2 CTA/SM) ------------
// mode 1: QKV epilogue (n<1024 -> split bf16 K|Q ; n>=1024 -> fp32 V)
// mode 2: C[m,n] += acc (accumulate into pre-filled out; no bias)
#define ROWB 80
#define TILEB (128 * ROWB)
#define STAGEB (4 * TILEB)          // 40960
#define GM_SMEM (2 * STAGEB)        // 81920

__global__ __launch_bounds__(256, 2) void gemm_mma(
    const __nv_bfloat16* __restrict__ Ahi, const __nv_bfloat16* __restrict__ Alo,
    const __nv_bfloat16* __restrict__ Bhi, const __nv_bfloat16* __restrict__ Blo,
    const float* __restrict__ bias, float* __restrict__ C, int Kd, int Nout, int mode)
{
    extern __shared__ char smem[];
    const uint32_t sbase = smem_u32(smem);
    const int tid = threadIdx.x;
    const int wid = tid >> 5, lane = tid & 31;
    const int warp_m = wid & 3, warp_n = wid >> 2;
    const int m0 = blockIdx.y * 128, n0 = blockIdx.x * 128;

    const int r0 = tid >> 2;
    const int r1 = r0 + 64;
    const int c0 = (tid & 3) * 16;
    const int ce = (tid & 3) * 8;

    auto load_stage = [&](int s, int k0) {
        uint32_t dst = sbase + (s & 1) * STAGEB;
        const __nv_bfloat16* srcs[4] = {
            Ahi + (size_t)(m0 + r0) * Kd + k0 + ce,
            Alo + (size_t)(m0 + r0) * Kd + k0 + ce,
            Bhi + (size_t)(n0 + r0) * Kd + k0 + ce,
            Blo + (size_t)(n0 + r0) * Kd + k0 + ce };
#pragma unroll
        for (int t = 0; t < 4; t++) {
            uint32_t d = dst + t * TILEB;
            CP_ASYNC16(d + r0 * ROWB + c0, srcs[t]);
            CP_ASYNC16(d + r1 * ROWB + c0, srcs[t] + (size_t)64 * Kd);
        }
        CP_COMMIT();
    };

    float acc[2][8][4] = {};
    const int nstages = Kd >> 5;
    load_stage(0, 0);

    for (int s = 0; s < nstages; s++) {
        if (s + 1 < nstages) { load_stage(s + 1, (s + 1) << 5); CP_WAIT1(); }
        else                 { CP_WAIT0(); }
        __syncthreads();

        const uint32_t st = sbase + (s & 1) * STAGEB;
        const uint32_t sAh = st, sAl = st + TILEB, sBh = st + 2 * TILEB, sBl = st + 3 * TILEB;

        const uint32_t aRow = (uint32_t)(warp_m * 32 + (lane & 15)) * ROWB + ((lane >> 4) & 1) * 16;
        const int g = lane >> 3, lr = lane & 7;
        const uint32_t bRowBase = (uint32_t)(warp_n * 64 + ((g >> 1) & 1) * 8 + lr) * ROWB + (g & 1) * 16;

#pragma unroll
        for (int ks = 0; ks < 2; ks++) {
            uint32_t ah[2][4], al[2][4];
#pragma unroll
            for (int mt = 0; mt < 2; mt++) {
                uint32_t ao = aRow + (uint32_t)mt * 16 * ROWB + ks * 32;
                ldm_x4(ah[mt], sAh + ao);
                ldm_x4(al[mt], sAl + ao);
            }
#pragma unroll
            for (int p = 0; p < 4; p++) {
                uint32_t bo = bRowBase + (uint32_t)p * 16 * ROWB + ks * 32;
                uint32_t bh[4], bl[4];
                ldm_x4(bh, sBh + bo);
                ldm_x4(bl, sBl + bo);
#pragma unroll
                for (int mt = 0; mt < 2; mt++)
#pragma unroll
                    for (int j = 0; j < 2; j++) {
                        float* cc = acc[mt][2 * p + j];
                        mma16816(cc, ah[mt], &bh[j * 2]);
                        mma16816(cc, ah[mt], &bl[j * 2]);
                        mma16816(cc, al[mt], &bh[j * 2]);
                    }
            }
        }
        __syncthreads();
    }

    const int mrow = m0 + warp_m * 32 + (lane >> 2);
    const int ncol0 = n0 + warp_n * 64 + (lane & 3) * 2;
#pragma unroll
    for (int mt = 0; mt < 2; mt++)
#pragma unroll
        for (int nt = 0; nt < 8; nt++) {
            int m = mrow + mt * 16;
            int n = ncol0 + nt * 8;
            const float* cc = acc[mt][nt];
            if (mode == 1) {
                float2 bv = *(const float2*)(bias + n);
                float x0 = cc[0] + bv.x, y0 = cc[1] + bv.y;
                float x1 = cc[2] + bv.x, y1 = cc[3] + bv.y;
                if (n < 1024) {
                    split_pair_store(x0, y0, g_kqh, g_kql, (size_t)m * 1024 + n);
                    split_pair_store(x1, y1, g_kqh, g_kql, (size_t)(m + 8) * 1024 + n);
                } else {
                    float2 v0; v0.x = x0; v0.y = y0;
                    float2 v1; v1.x = x1; v1.y = y1;
                    *(float2*)(g_V + (size_t)m * Ee + (n - 1024)) = v0;
                    *(float2*)(g_V + (size_t)(m + 8) * Ee + (n - 1024)) = v1;
                }
            } else {  // mode 2: accumulate
                float2 o0 = *(float2*)(C + (size_t)m * Nout + n);
                float2 o1 = *(float2*)(C + (size_t)(m + 8) * Nout + n);
                o0.x += cc[0]; o0.y += cc[1];
                o1.x += cc[2]; o1.y += cc[3];
                *(float2*)(C + (size_t)m * Nout + n) = o0;
                *(float2*)(C + (size_t)(m + 8) * Nout + n) = o1;
            }
        }
}

// ---------------- prep kernels ---------------------------------------------
#define XN   (MROWS * Ee)
#define W3N  (3 * Ee * Ee)
#define WU1N (Ee * Ee)

__global__ void prep_x(const float* __restrict__ x)
{
    for (int i = blockIdx.x * blockDim.x + threadIdx.x; i < XN; i += gridDim.x * blockDim.x) {
        float v = x[i];
        __nv_bfloat16 h = __float2bfloat16(v);
        g_xhi[i] = h;
        g_xlo[i] = __float2bfloat16(v - __bfloat162float(h));
    }
}
__global__ void prep_w(const float* __restrict__ Wk, const float* __restrict__ Wq,
                       const float* __restrict__ Wv, const float* __restrict__ Wu)
{
    for (int i = blockIdx.x * blockDim.x + threadIdx.x; i < W3N + WU1N; i += gridDim.x * blockDim.x) {
        if (i < W3N) {
            int wsel = i >> 18;
            int off = i & 262143;
            const float* W = (wsel == 0) ? Wk : (wsel == 1) ? Wq : Wv;
            float v = W[off];
            __nv_bfloat16 h = __float2bfloat16(v);
            g_Whi[i] = h;
            g_Wlo[i] = __float2bfloat16(v - __bfloat162float(h));
        } else {
            int off = i - W3N;
            int n = off >> 9, c = off & 511;       // Wu1 = Wu[:, 0:512]
            float v = Wu[(n << 10) + c];
            __nv_bfloat16 h = __float2bfloat16(v);
            g_Uhi[off] = h;
            g_Ulo[off] = __float2bfloat16(v - __bfloat162float(h));
        }
    }
}
__global__ void prep_bias(const float* __restrict__ bk, const float* __restrict__ bq,
                          const float* __restrict__ bv)
{
    int i = blockIdx.x * blockDim.x + threadIdx.x;
    if (i < Ee) {
        g_bias[i] = bk[i];
        g_bias[Ee + i] = bq[i];
        g_bias[2 * Ee + i] = bv[i];
    }
}

// store 4 fp32 as split hi/lo bf16 (comb)
__device__ __forceinline__ void store_split4(float* o, size_t off) {
    __nv_bfloat16 h[4], l[4];
#pragma unroll
    for (int j = 0; j < 4; j++) {
        h[j] = __float2bfloat16(o[j]);
        l[j] = __float2bfloat16(o[j] - __bfloat162float(h[j]));
    }
    *(uint2*)(g_chi + off) = *(uint2*)h;
    *(uint2*)(g_clo + off) = *(uint2*)l;
}

// ---------------- tensorized merged scores ---------------------------------
#define HS_AROWS 64
#define HS_ATILE (HS_AROWS * ROWB)
#define HS_BTILE (128 * ROWB)
#define HS_STAGE (2 * HS_ATILE + 2 * HS_BTILE)
#define HS_SMEM (2 * HS_STAGE)

__global__ __launch_bounds__(256) void hs_score_mma()
{
    extern __shared__ char smem[];
    const uint32_t sbase = smem_u32(smem);
    const int blk = blockIdx.x, b = blockIdx.y;
    const int tid = threadIdx.x;
    const int wid = tid >> 5, lane = tid & 31;
    const int warp_m = wid & 3;
    const int warp_n = wid >> 2;
    const size_t rbase = (size_t)b * Tt + (size_t)blk * KBLK;

    auto load_stage = [&](int s, int k0) {
        uint32_t dst = sbase + (uint32_t)(s & 1) * HS_STAGE;
#pragma unroll
        for (int j = 0; j < 6; j++) {
            int f = tid + j * 256;
            if (f < 512) {
                const __nv_bfloat16* base = (f < 256) ? g_kqh : g_kql;
                int r = (f >> 2) & 63, c = f & 3;
                CP_ASYNC16(dst + ((f < 256) ? 0u : (uint32_t)HS_ATILE) + r * ROWB + c * 16,
                           base + (rbase + r) * 1024 + k0 + c * 8);
            } else {
                int fb = f - 512;
                const __nv_bfloat16* base = (fb < 512) ? g_kqh : g_kql;
                int r = (fb >> 2) & 127, c = fb & 3;
                size_t tok = (size_t)b * Tt +
                    ((r < 64) ? (size_t)(blk * KBLK + r) : (size_t)((r & 31) * KBLK));
                CP_ASYNC16(dst + 2 * HS_ATILE + ((fb < 512) ? 0u : (uint32_t)HS_BTILE)
                               + r * ROWB + c * 16,
                           base + tok * 1024 + 512 + k0 + c * 8);
            }
        }
        CP_COMMIT();
    };

    float acc[8][4] = {};
    const int nstages = Ee >> 5;
    load_stage(0, 0);

    const uint32_t aRow = (uint32_t)(warp_m * 16 + (lane & 15)) * ROWB + ((lane >> 4) & 1) * 16;
    const int g = lane >> 3, lr = lane & 7;
    const uint32_t bRowBase = (uint32_t)(warp_n * 64 + ((g >> 1) & 1) * 8 + lr) * ROWB + (g & 1) * 16;

    for (int s = 0; s < nstages; s++) {
        if (s + 1 < nstages) { load_stage(s + 1, (s + 1) << 5); CP_WAIT1(); }
        else                 { CP_WAIT0(); }
        __syncthreads();

        const uint32_t st = sbase + (uint32_t)(s & 1) * HS_STAGE;
        const uint32_t sAh = st, sAl = st + HS_ATILE;
        const uint32_t sBh = st + 2 * HS_ATILE, sBl = sBh + HS_BTILE;

#pragma unroll
        for (int ks = 0; ks < 2; ks++) {
            uint32_t ah[4], al[4];
            uint32_t ao = aRow + ks * 32;
            ldm_x4(ah, sAh + ao);
            ldm_x4(al, sAl + ao);
#pragma unroll
            for (int p = 0; p < 4; p++) {
                uint32_t bo = bRowBase + (uint32_t)p * 16 * ROWB + ks * 32;
                uint32_t bh[4], bl[4];
                ldm_x4(bh, sBh + bo);
                ldm_x4(bl, sBl + bo);
#pragma unroll
                for (int j = 0; j < 2; j++) {
                    float* cc = acc[2 * p + j];
                    mma16816(cc, ah, &bh[j * 2]);
                    mma16816(cc, ah, &bl[j * 2]);
                    mma16816(cc, al, &bh[j * 2]);
                }
            }
        }
        __syncthreads();
    }

    float* d1 = g_S1 + ((size_t)b * NBLK + blk) * 4096;
    float* d2 = g_S2 + ((size_t)b * NBLK + blk) * 2048;
    const int rr = warp_m * 16 + (lane >> 2);
    const int cc0 = warp_n * 64 + (lane & 3) * 2;
#pragma unroll
    for (int nt = 0; nt < 8; nt++) {
        int c = cc0 + nt * 8;
        const float* cc = acc[nt];
        if (c < 64) {
            float2 v0; v0.x = cc[0]; v0.y = cc[1];
            float2 v1; v1.x = cc[2]; v1.y = cc[3];
            *(float2*)(d1 + rr * 64 + c) = v0;
            *(float2*)(d1 + (rr + 8) * 64 + c) = v1;
        } else if (c < 96) {
            float2 v0; v0.x = cc[0]; v0.y = cc[1];
            float2 v1; v1.x = cc[2]; v1.y = cc[3];
            *(float2*)(d2 + rr * 32 + (c - 64)) = v0;
            *(float2*)(d2 + (rr + 8) * 32 + (c - 64)) = v1;
        }
    }
}

// ---------------- M2 = V_starts @ Wu2^T  ([b][32][512], fp32) --------------
// grid (Ee/64, Bb), 256 threads: 64 n-cols, 32 i-rows
__global__ __launch_bounds__(256) void m2_kernel(const float* __restrict__ Wu)
{
    const int nc = blockIdx.x, b = blockIdx.y;
    const int tid = threadIdx.x;
    const int nl = tid & 63;          // n within chunk
    const int quad = tid >> 6;        // 0..3 -> 8 i's each

    __shared__ float Vs[32][64];      // [i][e]
    __shared__ float Ws[64][64];      // [e][n]

    float acc[8] = {};
    for (int e0 = 0; e0 < Ee; e0 += 64) {
        // V chunk: 32 rows x 64 e (float4 loads)
        for (int f = tid; f < 512; f += 256) {
            int i = f >> 4, c4 = (f & 15) * 4;
            *(float4*)&Vs[i][c4] =
                *(const float4*)(g_V + ((size_t)b * Tt + (size_t)i * KBLK) * Ee + e0 + c4);
        }
        // Wu2 chunk: 64 n x 64 e, stored transposed Ws[e][n]
        for (int f = tid; f < 1024; f += 256) {
            int n = f >> 4, c4 = (f & 15) * 4;
            float4 w = *(const float4*)(Wu + ((size_t)(nc * 64 + n) << 10) + 512 + e0 + c4);
            Ws[c4 + 0][n] = w.x; Ws[c4 + 1][n] = w.y;
            Ws[c4 + 2][n] = w.z; Ws[c4 + 3][n] = w.w;
        }
        __syncthreads();
#pragma unroll 8
        for (int e = 0; e < 64; e++) {
            float w = Ws[e][nl];
#pragma unroll
            for (int ii = 0; ii < 8; ii++)
                acc[ii] += Vs[quad * 8 + ii][e] * w;
        }
        __syncthreads();
    }
#pragma unroll
    for (int ii = 0; ii < 8; ii++)
        g_M2[((size_t)b * 32 + quad * 8 + ii) * Ee + nc * 64 + nl] = acc[ii];
}

// ---------------- out2: out = bu + masked(S2) @ M2  (covers ALL of out) ----
// grid (Ee/64, NBLK, Bb), 256 threads (16x16, 4x4 micro)
__global__ __launch_bounds__(256) void out2_kernel(const float* __restrict__ bu,
                                                   float* __restrict__ out)
{
    const int nc = blockIdx.x, rt = blockIdx.y, b = blockIdx.z;
    const int tid = threadIdx.x;
    const int ty = tid >> 4, tx = tid & 15;

    __shared__ float S2s[64][33];     // [r][i]
    __shared__ float Ms[32][64];      // [i][n]

    const float* sp = g_S2 + ((size_t)b * NBLK + rt) * 2048;
    for (int idx = tid; idx < 2048; idx += 256) {
        int r = idx >> 5, i = idx & 31;
        S2s[r][i] = sp[idx];
    }
    for (int idx = tid; idx < 2048; idx += 256) {
        int i = idx >> 6, n = idx & 63;
        Ms[i][n] = g_M2[((size_t)b * 32 + i) * Ee + nc * 64 + n];
    }
    __syncthreads();

    float acc[4][4] = {};
    for (int i = 0; i <= rt; i++) {
        float s_[4], m_[4];
#pragma unroll
        for (int u = 0; u < 4; u++) {
            s_[u] = S2s[ty * 4 + u][i];
            m_[u] = Ms[i][tx * 4 + u];
        }
#pragma unroll
        for (int u = 0; u < 4; u++)
#pragma unroll
            for (int v = 0; v < 4; v++)
                acc[u][v] += s_[u] * m_[v];
    }

    float4 bv = *(const float4*)(bu + nc * 64 + tx * 4);
    const size_t rowb = (size_t)b * Tt + (size_t)rt * KBLK;
#pragma unroll
    for (int u = 0; u < 4; u++) {
        float4 v;
        v.x = acc[u][0] + bv.x; v.y = acc[u][1] + bv.y;
        v.z = acc[u][2] + bv.z; v.w = acc[u][3] + bv.w;
        *(float4*)(out + (rowb + ty * 4 + u) * Ee + nc * 64 + tx * 4) = v;
    }
}

// ---------------- head1: output (e-split) -> split bf16 comb (512 wide) ----
__global__ __launch_bounds__(256) void h1_out()
{
    const int blk = blockIdx.x, b = blockIdx.y, ec = blockIdx.z;
    const int tid = threadIdx.x;
    const int ty = tid >> 4, tx = tid & 15;
    const size_t rbase = (size_t)b * Tt + (size_t)blk * KBLK;

    __shared__ float Ssh[64][68];
    __shared__ float Vs[64][68];

    const float* sp = g_S1 + ((size_t)b * NBLK + blk) * 4096;
    for (int idx = tid; idx < 4096; idx += 256) {
        int r = idx >> 6, c = idx & 63;
        Ssh[c][r] = (c <= r) ? sp[idx] : 0.0f;
    }
    __syncthreads();

    const int ebeg = ec * (Ee / ESPL);
    for (int e0 = ebeg; e0 < ebeg + Ee / ESPL; e0 += 64) {
#pragma unroll
        for (int l = 0; l < 4; l++) {
            int c = ty + l * 16;
            *(float4*)&Vs[c][tx * 4] =
                *(const float4*)(g_V + (rbase + c) * Ee + e0 + tx * 4);
        }
        __syncthreads();
        float o[4][4] = {};
#pragma unroll 8
        for (int c = 0; c < 64; c++) {
            float4 rs = *(const float4*)&Ssh[c][ty * 4];
            float4 rv = *(const float4*)&Vs[c][tx * 4];
            float s_[4] = {rs.x, rs.y, rs.z, rs.w};
            float v_[4] = {rv.x, rv.y, rv.z, rv.w};
#pragma unroll
            for (int i = 0; i < 4; i++)
#pragma unroll
                for (int j = 0; j < 4; j++)
                    o[i][j] += s_[i] * v_[j];
        }
#pragma unroll
        for (int i = 0; i < 4; i++) {
            size_t row = rbase + ty * 4 + i;
            store_split4(o[i], row * Ee + e0 + tx * 4);
        }
        __syncthreads();
    }
}

// ---------------------------------------------------------------------------
extern "C" void kernel_launch(void* const* d_in, const int* in_sizes, int n_in,
                              void* d_out, int out_size)
{
    const float* x  = (const float*)d_in[0];
    const float* Wk = (const float*)d_in[1];
    const float* bk = (const float*)d_in[2];
    const float* Wq = (const float*)d_in[3];
    const float* bq = (const float*)d_in[4];
    const float* Wv = (const float*)d_in[5];
    const float* bv = (const float*)d_in[6];
    const float* Wu = (const float*)d_in[7];
    const float* bu = (const float*)d_in[8];
    float* out = (float*)d_out;

    float *pBias;
    __nv_bfloat16 *pxh, *pxl, *pWh, *pWl, *pUh, *pUl, *pch, *pcl;
    cudaGetSymbolAddress((void**)&pBias, g_bias);
    cudaGetSymbolAddress((void**)&pxh, g_xhi);
    cudaGetSymbolAddress((void**)&pxl, g_xlo);
    cudaGetSymbolAddress((void**)&pWh, g_Whi);
    cudaGetSymbolAddress((void**)&pWl, g_Wlo);
    cudaGetSymbolAddress((void**)&pUh, g_Uhi);
    cudaGetSymbolAddress((void**)&pUl, g_Ulo);
    cudaGetSymbolAddress((void**)&pch, g_chi);
    cudaGetSymbolAddress((void**)&pcl, g_clo);

    cudaFuncSetAttribute(gemm_mma, cudaFuncAttributeMaxDynamicSharedMemorySize, GM_SMEM);
    cudaFuncSetAttribute(hs_score_mma, cudaFuncAttributeMaxDynamicSharedMemorySize, HS_SMEM);

    // launches 1-3: prep
    prep_x<<<1024, 256>>>(x);
    prep_w<<<640, 256>>>(Wk, Wq, Wv, Wu);
    prep_bias<<<2, 256>>>(bk, bq, bv);

    // launch 4: fused QKV projection -> split bf16 K|Q + fp32 V  (profiled)
    gemm_mma<<<dim3(NQKV / 128, MROWS / 128), 256, GM_SMEM>>>(
        pxh, pxl, pWh, pWl, pBias, nullptr, Ee, NQKV, 1);

    // launch 5: tensorized merged scores
    hs_score_mma<<<dim3(NBLK, Bb), 256, HS_SMEM>>>();

    // launch 6: M2 = V_starts @ Wu2^T (tiny fp32)
    m2_kernel<<<dim3(Ee / 64, Bb), 256>>>(Wu);

    // launch 7: h1 output -> split bf16 comb
    h1_out<<<dim3(NBLK, Bb, ESPL), 256>>>();

    // launch 8: out = bu + masked(S2) @ M2  (fills all of d_out)
    out2_kernel<<<dim3(Ee / 64, NBLK, Bb), 256>>>(bu, out);

    // launch 9: out += h1 @ Wu1^T  (K=512, accumulate)
    gemm_mma<<<dim3(Ee / 128, MROWS / 128), 256, GM_SMEM>>>(
        pch, pcl, pUh, pUl, pBias, out, Ee, Ee, 2);
}

// round 12
// speedup vs baseline: 1.0015x; 1.0015x over previous
#include <cuda_runtime.h>
#include <cuda_bf16.h>
#include <cstdint>

#define Bb 4
#define Tt 2048
#define Ee 512
#define KBLK 64
#define NBLK 32
#define MROWS (Bb * Tt)        // 8192
#define NQKV (3 * Ee)          // 1536
#define ESPL 4

// ---------------- scratch (__device__ globals) ------------------------------
__device__ __nv_bfloat16 g_xhi[MROWS * Ee];
__device__ __nv_bfloat16 g_xlo[MROWS * Ee];
__device__ __nv_bfloat16 g_Whi[NQKV * Ee];
__device__ __nv_bfloat16 g_Wlo[NQKV * Ee];
__device__ __nv_bfloat16 g_Uhi[Ee * Ee];           // Wu1 (cols 0..511) split hi
__device__ __nv_bfloat16 g_Ulo[Ee * Ee];
__device__ __nv_bfloat16 g_chi[MROWS * Ee];        // comb = h1 only (512 wide)
__device__ __nv_bfloat16 g_clo[MROWS * Ee];
__device__ __nv_bfloat16 g_kqh[MROWS * 1024];      // K|Q bf16 hi (stride 1024)
__device__ __nv_bfloat16 g_kql[MROWS * 1024];      // K|Q bf16 lo
__device__ float g_V[MROWS * Ee];                  // V fp32 (stride 512)
__device__ float g_bias[NQKV];
__device__ float g_S1[Bb * NBLK * 64 * 64];        // 2 MB
__device__ float g_S2[Bb * NBLK * 64 * 32];        // 1 MB
__device__ float g_M2[Bb * 32 * Ee];               // V_starts @ Wu2^T

// ---------------- PTX helpers ----------------------------------------------
__device__ __forceinline__ uint32_t smem_u32(const void* p) {
    uint32_t a;
    asm("{ .reg .u64 t; cvta.to.shared.u64 t, %1; cvt.u32.u64 %0, t; }"
        : "=r"(a) : "l"(p));
    return a;
}
#define CP_ASYNC16(dst, src) \
    asm volatile("cp.async.cg.shared.global [%0], [%1], 16;" :: "r"(dst), "l"(src))
#define CP_COMMIT() asm volatile("cp.async.commit_group;" ::: "memory")
#define CP_WAIT1()  asm volatile("cp.async.wait_group 1;" ::: "memory")
#define CP_WAIT0()  asm volatile("cp.async.wait_group 0;" ::: "memory")

__device__ __forceinline__ void ldm_x4(uint32_t* r, uint32_t addr) {
    asm volatile("ldmatrix.sync.aligned.m8n8.x4.shared.b16 {%0,%1,%2,%3}, [%4];"
                 : "=r"(r[0]), "=r"(r[1]), "=r"(r[2]), "=r"(r[3]) : "r"(addr));
}
__device__ __forceinline__ void mma16816(float* c, const uint32_t* a, const uint32_t* b) {
    asm volatile("mma.sync.aligned.m16n8k16.row.col.f32.bf16.bf16.f32 "
                 "{%0,%1,%2,%3}, {%4,%5,%6,%7}, {%8,%9}, {%0,%1,%2,%3};"
                 : "+f"(c[0]), "+f"(c[1]), "+f"(c[2]), "+f"(c[3])
                 : "r"(a[0]), "r"(a[1]), "r"(a[2]), "r"(a[3]), "r"(b[0]), "r"(b[1]));
}

__device__ __forceinline__ void split_pair_store(
    float x, float y, __nv_bfloat16* hi, __nv_bfloat16* lo, size_t off)
{
    __nv_bfloat16 h0 = __float2bfloat16(x);
    __nv_bfloat16 h1 = __float2bfloat16(y);
    __nv_bfloat16 l0 = __float2bfloat16(x - __bfloat162float(h0));
    __nv_bfloat16 l1 = __float2bfloat16(y - __bfloat162float(h1));
    __nv_bfloat162 hh; hh.x = h0; hh.y = h1;
    __nv_bfloat162 ll; ll.x = l0; ll.y = l1;
    *(__nv_bfloat162*)(hi + off) = hh;
    *(__nv_bfloat162*)(lo + off) = ll;
}

// ---------------- split-bf16 NT GEMM (BK=32, 2-stage, 2 CTA/SM) ------------
// mode 1: QKV epilogue (n<1024 -> split bf16 K|Q ; n>=1024 -> fp32 V)
// mode 2: C[m,n] += acc
#define ROWB 80
#define TILEB (128 * ROWB)
#define STAGEB (4 * TILEB)          // 40960
#define GM_SMEM (2 * STAGEB)        // 81920

__global__ __launch_bounds__(256, 2) void gemm_mma(
    const __nv_bfloat16* __restrict__ Ahi, const __nv_bfloat16* __restrict__ Alo,
    const __nv_bfloat16* __restrict__ Bhi, const __nv_bfloat16* __restrict__ Blo,
    const float* __restrict__ bias, float* __restrict__ C, int Kd, int Nout, int mode)
{
    extern __shared__ char smem[];
    const uint32_t sbase = smem_u32(smem);
    const int tid = threadIdx.x;
    const int wid = tid >> 5, lane = tid & 31;
    const int warp_m = wid & 3, warp_n = wid >> 2;
    const int m0 = blockIdx.y * 128, n0 = blockIdx.x * 128;

    const int r0 = tid >> 2;
    const int r1 = r0 + 64;
    const int c0 = (tid & 3) * 16;
    const int ce = (tid & 3) * 8;

    auto load_stage = [&](int s, int k0) {
        uint32_t dst = sbase + (s & 1) * STAGEB;
        const __nv_bfloat16* srcs[4] = {
            Ahi + (size_t)(m0 + r0) * Kd + k0 + ce,
            Alo + (size_t)(m0 + r0) * Kd + k0 + ce,
            Bhi + (size_t)(n0 + r0) * Kd + k0 + ce,
            Blo + (size_t)(n0 + r0) * Kd + k0 + ce };
#pragma unroll
        for (int t = 0; t < 4; t++) {
            uint32_t d = dst + t * TILEB;
            CP_ASYNC16(d + r0 * ROWB + c0, srcs[t]);
            CP_ASYNC16(d + r1 * ROWB + c0, srcs[t] + (size_t)64 * Kd);
        }
        CP_COMMIT();
    };

    float acc[2][8][4] = {};
    const int nstages = Kd >> 5;
    load_stage(0, 0);

    for (int s = 0; s < nstages; s++) {
        if (s + 1 < nstages) { load_stage(s + 1, (s + 1) << 5); CP_WAIT1(); }
        else                 { CP_WAIT0(); }
        __syncthreads();

        const uint32_t st = sbase + (s & 1) * STAGEB;
        const uint32_t sAh = st, sAl = st + TILEB, sBh = st + 2 * TILEB, sBl = st + 3 * TILEB;

        const uint32_t aRow = (uint32_t)(warp_m * 32 + (lane & 15)) * ROWB + ((lane >> 4) & 1) * 16;
        const int g = lane >> 3, lr = lane & 7;
        const uint32_t bRowBase = (uint32_t)(warp_n * 64 + ((g >> 1) & 1) * 8 + lr) * ROWB + (g & 1) * 16;

#pragma unroll
        for (int ks = 0; ks < 2; ks++) {
            uint32_t ah[2][4], al[2][4];
#pragma unroll
            for (int mt = 0; mt < 2; mt++) {
                uint32_t ao = aRow + (uint32_t)mt * 16 * ROWB + ks * 32;
                ldm_x4(ah[mt], sAh + ao);
                ldm_x4(al[mt], sAl + ao);
            }
#pragma unroll
            for (int p = 0; p < 4; p++) {
                uint32_t bo = bRowBase + (uint32_t)p * 16 * ROWB + ks * 32;
                uint32_t bh[4], bl[4];
                ldm_x4(bh, sBh + bo);
                ldm_x4(bl, sBl + bo);
                // product-major order: same-acc RAW distance 4 (was 1)
#pragma unroll
                for (int mt = 0; mt < 2; mt++)
#pragma unroll
                    for (int j = 0; j < 2; j++)
                        mma16816(acc[mt][2 * p + j], ah[mt], &bh[j * 2]);
#pragma unroll
                for (int mt = 0; mt < 2; mt++)
#pragma unroll
                    for (int j = 0; j < 2; j++)
                        mma16816(acc[mt][2 * p + j], ah[mt], &bl[j * 2]);
#pragma unroll
                for (int mt = 0; mt < 2; mt++)
#pragma unroll
                    for (int j = 0; j < 2; j++)
                        mma16816(acc[mt][2 * p + j], al[mt], &bh[j * 2]);
            }
        }
        __syncthreads();
    }

    const int mrow = m0 + warp_m * 32 + (lane >> 2);
    const int ncol0 = n0 + warp_n * 64 + (lane & 3) * 2;
#pragma unroll
    for (int mt = 0; mt < 2; mt++)
#pragma unroll
        for (int nt = 0; nt < 8; nt++) {
            int m = mrow + mt * 16;
            int n = ncol0 + nt * 8;
            const float* cc = acc[mt][nt];
            if (mode == 1) {
                float2 bv = *(const float2*)(bias + n);
                float x0 = cc[0] + bv.x, y0 = cc[1] + bv.y;
                float x1 = cc[2] + bv.x, y1 = cc[3] + bv.y;
                if (n < 1024) {
                    split_pair_store(x0, y0, g_kqh, g_kql, (size_t)m * 1024 + n);
                    split_pair_store(x1, y1, g_kqh, g_kql, (size_t)(m + 8) * 1024 + n);
                } else {
                    float2 v0; v0.x = x0; v0.y = y0;
                    float2 v1; v1.x = x1; v1.y = y1;
                    *(float2*)(g_V + (size_t)m * Ee + (n - 1024)) = v0;
                    *(float2*)(g_V + (size_t)(m + 8) * Ee + (n - 1024)) = v1;
                }
            } else {  // mode 2: accumulate
                float2 o0 = *(float2*)(C + (size_t)m * Nout + n);
                float2 o1 = *(float2*)(C + (size_t)(m + 8) * Nout + n);
                o0.x += cc[0]; o0.y += cc[1];
                o1.x += cc[2]; o1.y += cc[3];
                *(float2*)(C + (size_t)m * Nout + n) = o0;
                *(float2*)(C + (size_t)(m + 8) * Nout + n) = o1;
            }
        }
}

// ---------------- prep kernels ---------------------------------------------
#define XN   (MROWS * Ee)
#define W3N  (3 * Ee * Ee)
#define WU1N (Ee * Ee)

__global__ void prep_x(const float* __restrict__ x)
{
    for (int i = blockIdx.x * blockDim.x + threadIdx.x; i < XN; i += gridDim.x * blockDim.x) {
        float v = x[i];
        __nv_bfloat16 h = __float2bfloat16(v);
        g_xhi[i] = h;
        g_xlo[i] = __float2bfloat16(v - __bfloat162float(h));
    }
}
__global__ void prep_w(const float* __restrict__ Wk, const float* __restrict__ Wq,
                       const float* __restrict__ Wv, const float* __restrict__ Wu)
{
    for (int i = blockIdx.x * blockDim.x + threadIdx.x; i < W3N + WU1N; i += gridDim.x * blockDim.x) {
        if (i < W3N) {
            int wsel = i >> 18;
            int off = i & 262143;
            const float* W = (wsel == 0) ? Wk : (wsel == 1) ? Wq : Wv;
            float v = W[off];
            __nv_bfloat16 h = __float2bfloat16(v);
            g_Whi[i] = h;
            g_Wlo[i] = __float2bfloat16(v - __bfloat162float(h));
        } else {
            int off = i - W3N;
            int n = off >> 9, c = off & 511;       // Wu1 = Wu[:, 0:512]
            float v = Wu[(n << 10) + c];
            __nv_bfloat16 h = __float2bfloat16(v);
            g_Uhi[off] = h;
            g_Ulo[off] = __float2bfloat16(v - __bfloat162float(h));
        }
    }
}
__global__ void prep_bias(const float* __restrict__ bk, const float* __restrict__ bq,
                          const float* __restrict__ bv)
{
    int i = blockIdx.x * blockDim.x + threadIdx.x;
    if (i < Ee) {
        g_bias[i] = bk[i];
        g_bias[Ee + i] = bq[i];
        g_bias[2 * Ee + i] = bv[i];
    }
}

// store 4 fp32 as split hi/lo bf16 (comb)
__device__ __forceinline__ void store_split4(float* o, size_t off) {
    __nv_bfloat16 h[4], l[4];
#pragma unroll
    for (int j = 0; j < 4; j++) {
        h[j] = __float2bfloat16(o[j]);
        l[j] = __float2bfloat16(o[j] - __bfloat162float(h[j]));
    }
    *(uint2*)(g_chi + off) = *(uint2*)h;
    *(uint2*)(g_clo + off) = *(uint2*)l;
}

// ---------------- tensorized merged scores ---------------------------------
#define HS_AROWS 64
#define HS_ATILE (HS_AROWS * ROWB)
#define HS_BTILE (128 * ROWB)
#define HS_STAGE (2 * HS_ATILE + 2 * HS_BTILE)
#define HS_SMEM (2 * HS_STAGE)

__global__ __launch_bounds__(256) void hs_score_mma()
{
    extern __shared__ char smem[];
    const uint32_t sbase = smem_u32(smem);
    const int blk = blockIdx.x, b = blockIdx.y;
    const int tid = threadIdx.x;
    const int wid = tid >> 5, lane = tid & 31;
    const int warp_m = wid & 3;
    const int warp_n = wid >> 2;
    const size_t rbase = (size_t)b * Tt + (size_t)blk * KBLK;

    auto load_stage = [&](int s, int k0) {
        uint32_t dst = sbase + (uint32_t)(s & 1) * HS_STAGE;
#pragma unroll
        for (int j = 0; j < 6; j++) {
            int f = tid + j * 256;
            if (f < 512) {
                const __nv_bfloat16* base = (f < 256) ? g_kqh : g_kql;
                int r = (f >> 2) & 63, c = f & 3;
                CP_ASYNC16(dst + ((f < 256) ? 0u : (uint32_t)HS_ATILE) + r * ROWB + c * 16,
                           base + (rbase + r) * 1024 + k0 + c * 8);
            } else {
                int fb = f - 512;
                const __nv_bfloat16* base = (fb < 512) ? g_kqh : g_kql;
                int r = (fb >> 2) & 127, c = fb & 3;
                size_t tok = (size_t)b * Tt +
                    ((r < 64) ? (size_t)(blk * KBLK + r) : (size_t)((r & 31) * KBLK));
                CP_ASYNC16(dst + 2 * HS_ATILE + ((fb < 512) ? 0u : (uint32_t)HS_BTILE)
                               + r * ROWB + c * 16,
                           base + tok * 1024 + 512 + k0 + c * 8);
            }
        }
        CP_COMMIT();
    };

    float acc[8][4] = {};
    const int nstages = Ee >> 5;
    load_stage(0, 0);

    const uint32_t aRow = (uint32_t)(warp_m * 16 + (lane & 15)) * ROWB + ((lane >> 4) & 1) * 16;
    const int g = lane >> 3, lr = lane & 7;
    const uint32_t bRowBase = (uint32_t)(warp_n * 64 + ((g >> 1) & 1) * 8 + lr) * ROWB + (g & 1) * 16;

    for (int s = 0; s < nstages; s++) {
        if (s + 1 < nstages) { load_stage(s + 1, (s + 1) << 5); CP_WAIT1(); }
        else                 { CP_WAIT0(); }
        __syncthreads();

        const uint32_t st = sbase + (uint32_t)(s & 1) * HS_STAGE;
        const uint32_t sAh = st, sAl = st + HS_ATILE;
        const uint32_t sBh = st + 2 * HS_ATILE, sBl = sBh + HS_BTILE;

#pragma unroll
        for (int ks = 0; ks < 2; ks++) {
            uint32_t ah[4], al[4];
            uint32_t ao = aRow + ks * 32;
            ldm_x4(ah, sAh + ao);
            ldm_x4(al, sAl + ao);
            // hold both p's B frags; product-major order (RAW distance 4)
            uint32_t bh[2][4], bl[2][4];
#pragma unroll
            for (int p = 0; p < 2; p++) {
                uint32_t bo = bRowBase + (uint32_t)(2 * p) * 16 * ROWB + ks * 32;
                // note: p here covers the 4 original p's in pairs via two passes
                ldm_x4(bh[p], sBh + bo);
                ldm_x4(bl[p], sBl + bo);
            }
#pragma unroll
            for (int p = 0; p < 2; p++)
#pragma unroll
                for (int j = 0; j < 2; j++)
                    mma16816(acc[4 * p + j], ah, &bh[p][j * 2]);
#pragma unroll
            for (int p = 0; p < 2; p++)
#pragma unroll
                for (int j = 0; j < 2; j++)
                    mma16816(acc[4 * p + j], ah, &bl[p][j * 2]);
#pragma unroll
            for (int p = 0; p < 2; p++)
#pragma unroll
                for (int j = 0; j < 2; j++)
                    mma16816(acc[4 * p + j], al, &bh[p][j * 2]);
            // second pair of p (original p = 1, 3)
#pragma unroll
            for (int p = 0; p < 2; p++) {
                uint32_t bo = bRowBase + (uint32_t)(2 * p + 1) * 16 * ROWB + ks * 32;
                ldm_x4(bh[p], sBh + bo);
                ldm_x4(bl[p], sBl + bo);
            }
#pragma unroll
            for (int p = 0; p < 2; p++)
#pragma unroll
                for (int j = 0; j < 2; j++)
                    mma16816(acc[4 * p + 2 + j], ah, &bh[p][j * 2]);
#pragma unroll
            for (int p = 0; p < 2; p++)
#pragma unroll
                for (int j = 0; j < 2; j++)
                    mma16816(acc[4 * p + 2 + j], ah, &bl[p][j * 2]);
#pragma unroll
            for (int p = 0; p < 2; p++)
#pragma unroll
                for (int j = 0; j < 2; j++)
                    mma16816(acc[4 * p + 2 + j], al, &bh[p][j * 2]);
        }
        __syncthreads();
    }

    float* d1 = g_S1 + ((size_t)b * NBLK + blk) * 4096;
    float* d2 = g_S2 + ((size_t)b * NBLK + blk) * 2048;
    const int rr = warp_m * 16 + (lane >> 2);
    const int cc0 = warp_n * 64 + (lane & 3) * 2;
#pragma unroll
    for (int nt = 0; nt < 8; nt++) {
        // acc index mapping: nt -> original column tile order
        // original p0..3 cols: p*16; acc[4*pp + 2*half + j] covers (2*pp + half)*16...
        // We stored: acc[4*p + j] for orig p' = 2p (cols p'*16), acc[4*p+2+j] for p' = 2p+1.
        int pp = nt >> 2;           // 0,1
        int sub = nt & 3;           // 0..3: [p'=2pp j0, j1, p'=2pp+1 j0, j1]
        int porig = 2 * pp + (sub >> 1);
        int j = sub & 1;
        int c = cc0 - (lane & 3) * 2;  // warp_n*64 base
        c = warp_n * 64 + porig * 16 + j * 8 + (lane & 3) * 2;
        const float* cc = acc[nt];
        if (c < 64) {
            float2 v0; v0.x = cc[0]; v0.y = cc[1];
            float2 v1; v1.x = cc[2]; v1.y = cc[3];
            *(float2*)(d1 + rr * 64 + c) = v0;
            *(float2*)(d1 + (rr + 8) * 64 + c) = v1;
        } else if (c < 96) {
            float2 v0; v0.x = cc[0]; v0.y = cc[1];
            float2 v1; v1.x = cc[2]; v1.y = cc[3];
            *(float2*)(d2 + rr * 32 + (c - 64)) = v0;
            *(float2*)(d2 + (rr + 8) * 32 + (c - 64)) = v1;
        }
    }
}

// ---------------- M2 = V_starts @ Wu2^T  ([b][32][512], fp32) --------------
__global__ __launch_bounds__(256) void m2_kernel(const float* __restrict__ Wu)
{
    const int nc = blockIdx.x, b = blockIdx.y;
    const int tid = threadIdx.x;
    const int nl = tid & 63;
    const int quad = tid >> 6;

    __shared__ float Vs[32][64];
    __shared__ float Ws[64][64];

    float acc[8] = {};
    for (int e0 = 0; e0 < Ee; e0 += 64) {
        for (int f = tid; f < 512; f += 256) {
            int i = f >> 4, c4 = (f & 15) * 4;
            *(float4*)&Vs[i][c4] =
                *(const float4*)(g_V + ((size_t)b * Tt + (size_t)i * KBLK) * Ee + e0 + c4);
        }
        for (int f = tid; f < 1024; f += 256) {
            int n = f >> 4, c4 = (f & 15) * 4;
            float4 w = *(const float4*)(Wu + ((size_t)(nc * 64 + n) << 10) + 512 + e0 + c4);
            Ws[c4 + 0][n] = w.x; Ws[c4 + 1][n] = w.y;
            Ws[c4 + 2][n] = w.z; Ws[c4 + 3][n] = w.w;
        }
        __syncthreads();
#pragma unroll 8
        for (int e = 0; e < 64; e++) {
            float w = Ws[e][nl];
#pragma unroll
            for (int ii = 0; ii < 8; ii++)
                acc[ii] += Vs[quad * 8 + ii][e] * w;
        }
        __syncthreads();
    }
#pragma unroll
    for (int ii = 0; ii < 8; ii++)
        g_M2[((size_t)b * 32 + quad * 8 + ii) * Ee + nc * 64 + nl] = acc[ii];
}

// ---------------- out2: out = bu + masked(S2) @ M2 -------------------------
__global__ __launch_bounds__(256) void out2_kernel(const float* __restrict__ bu,
                                                   float* __restrict__ out)
{
    const int nc = blockIdx.x, rt = blockIdx.y, b = blockIdx.z;
    const int tid = threadIdx.x;
    const int ty = tid >> 4, tx = tid & 15;

    __shared__ float S2s[64][33];
    __shared__ float Ms[32][64];

    const float* sp = g_S2 + ((size_t)b * NBLK + rt) * 2048;
    for (int idx = tid; idx < 2048; idx += 256) {
        int r = idx >> 5, i = idx & 31;
        S2s[r][i] = sp[idx];
    }
    for (int idx = tid; idx < 2048; idx += 256) {
        int i = idx >> 6, n = idx & 63;
        Ms[i][n] = g_M2[((size_t)b * 32 + i) * Ee + nc * 64 + n];
    }
    __syncthreads();

    float acc[4][4] = {};
    for (int i = 0; i <= rt; i++) {
        float s_[4], m_[4];
#pragma unroll
        for (int u = 0; u < 4; u++) {
            s_[u] = S2s[ty * 4 + u][i];
            m_[u] = Ms[i][tx * 4 + u];
        }
#pragma unroll
        for (int u = 0; u < 4; u++)
#pragma unroll
            for (int v = 0; v < 4; v++)
                acc[u][v] += s_[u] * m_[v];
    }

    float4 bv = *(const float4*)(bu + nc * 64 + tx * 4);
    const size_t rowb = (size_t)b * Tt + (size_t)rt * KBLK;
#pragma unroll
    for (int u = 0; u < 4; u++) {
        float4 v;
        v.x = acc[u][0] + bv.x; v.y = acc[u][1] + bv.y;
        v.z = acc[u][2] + bv.z; v.w = acc[u][3] + bv.w;
        *(float4*)(out + (rowb + ty * 4 + u) * Ee + nc * 64 + tx * 4) = v;
    }
}

// ---------------- head1: output (e-split) -> split bf16 comb ---------------
__global__ __launch_bounds__(256) void h1_out()
{
    const int blk = blockIdx.x, b = blockIdx.y, ec = blockIdx.z;
    const int tid = threadIdx.x;
    const int ty = tid >> 4, tx = tid & 15;
    const size_t rbase = (size_t)b * Tt + (size_t)blk * KBLK;

    __shared__ float Ssh[64][68];
    __shared__ float Vs[64][68];

    const float* sp = g_S1 + ((size_t)b * NBLK + blk) * 4096;
    for (int idx = tid; idx < 4096; idx += 256) {
        int r = idx >> 6, c = idx & 63;
        Ssh[c][r] = (c <= r) ? sp[idx] : 0.0f;
    }
    __syncthreads();

    const int ebeg = ec * (Ee / ESPL);
    for (int e0 = ebeg; e0 < ebeg + Ee / ESPL; e0 += 64) {
#pragma unroll
        for (int l = 0; l < 4; l++) {
            int c = ty + l * 16;
            *(float4*)&Vs[c][tx * 4] =
                *(const float4*)(g_V + (rbase + c) * Ee + e0 + tx * 4);
        }
        __syncthreads();
        float o[4][4] = {};
#pragma unroll 8
        for (int c = 0; c < 64; c++) {
            float4 rs = *(const float4*)&Ssh[c][ty * 4];
            float4 rv = *(const float4*)&Vs[c][tx * 4];
            float s_[4] = {rs.x, rs.y, rs.z, rs.w};
            float v_[4] = {rv.x, rv.y, rv.z, rv.w};
#pragma unroll
            for (int i = 0; i < 4; i++)
#pragma unroll
                for (int j = 0; j < 4; j++)
                    o[i][j] += s_[i] * v_[j];
        }
#pragma unroll
        for (int i = 0; i < 4; i++) {
            size_t row = rbase + ty * 4 + i;
            store_split4(o[i], row * Ee + e0 + tx * 4);
        }
        __syncthreads();
    }
}

// ---------------------------------------------------------------------------
extern "C" void kernel_launch(void* const* d_in, const int* in_sizes, int n_in,
                              void* d_out, int out_size)
{
    const float* x  = (const float*)d_in[0];
    const float* Wk = (const float*)d_in[1];
    const float* bk = (const float*)d_in[2];
    const float* Wq = (const float*)d_in[3];
    const float* bq = (const float*)d_in[4];
    const float* Wv = (const float*)d_in[5];
    const float* bv = (const float*)d_in[6];
    const float* Wu = (const float*)d_in[7];
    const float* bu = (const float*)d_in[8];
    float* out = (float*)d_out;

    float *pBias;
    __nv_bfloat16 *pxh, *pxl, *pWh, *pWl, *pUh, *pUl, *pch, *pcl;
    cudaGetSymbolAddress((void**)&pBias, g_bias);
    cudaGetSymbolAddress((void**)&pxh, g_xhi);
    cudaGetSymbolAddress((void**)&pxl, g_xlo);
    cudaGetSymbolAddress((void**)&pWh, g_Whi);
    cudaGetSymbolAddress((void**)&pWl, g_Wlo);
    cudaGetSymbolAddress((void**)&pUh, g_Uhi);
    cudaGetSymbolAddress((void**)&pUl, g_Ulo);
    cudaGetSymbolAddress((void**)&pch, g_chi);
    cudaGetSymbolAddress((void**)&pcl, g_clo);

    cudaFuncSetAttribute(gemm_mma, cudaFuncAttributeMaxDynamicSharedMemorySize, GM_SMEM);
    cudaFuncSetAttribute(hs_score_mma, cudaFuncAttributeMaxDynamicSharedMemorySize, HS_SMEM);

    // launches 1-3: prep
    prep_x<<<1024, 256>>>(x);
    prep_w<<<640, 256>>>(Wk, Wq, Wv, Wu);
    prep_bias<<<2, 256>>>(bk, bq, bv);

    // launch 4: fused QKV projection (profiled)
    gemm_mma<<<dim3(NQKV / 128, MROWS / 128), 256, GM_SMEM>>>(
        pxh, pxl, pWh, pWl, pBias, nullptr, Ee, NQKV, 1);

    // launch 5: tensorized merged scores
    hs_score_mma<<<dim3(NBLK, Bb), 256, HS_SMEM>>>();

    // launch 6: M2 = V_starts @ Wu2^T
    m2_kernel<<<dim3(Ee / 64, Bb), 256>>>(Wu);

    // launch 7: h1 output -> split bf16 comb
    h1_out<<<dim3(NBLK, Bb, ESPL), 256>>>();

    // launch 8: out = bu + masked(S2) @ M2
    out2_kernel<<<dim3(Ee / 64, NBLK, Bb), 256>>>(bu, out);

    // launch 9: out += h1 @ Wu1^T
    gemm_mma<<<dim3(Ee / 128, MROWS / 128), 256, GM_SMEM>>>(
        pch, pcl, pUh, pUl, pBias, out, Ee, Ee, 2);
}

// round 13
// speedup vs baseline: 1.0100x; 1.0085x over previous
#include <cuda_runtime.h>
#include <cuda_bf16.h>
#include <cstdint>

#define Bb 4
#define Tt 2048
#define Ee 512
#define KBLK 64
#define NBLK 32
#define MROWS (Bb * Tt)        // 8192
#define NQKV (3 * Ee)          // 1536

// ---------------- scratch (__device__ globals) ------------------------------
__device__ __nv_bfloat16 g_xhi[MROWS * Ee];
__device__ __nv_bfloat16 g_xlo[MROWS * Ee];
__device__ __nv_bfloat16 g_Whi[NQKV * Ee];
__device__ __nv_bfloat16 g_Wlo[NQKV * Ee];
__device__ __nv_bfloat16 g_Uhi[Ee * Ee];           // Wu1 split hi
__device__ __nv_bfloat16 g_Ulo[Ee * Ee];
__device__ __nv_bfloat16 g_chi[MROWS * Ee];        // comb = h1 (512 wide)
__device__ __nv_bfloat16 g_clo[MROWS * Ee];
__device__ __nv_bfloat16 g_kqh[MROWS * 1024];
__device__ __nv_bfloat16 g_kql[MROWS * 1024];
__device__ float g_V[MROWS * Ee];
__device__ float g_bias[NQKV];
__device__ float g_S1[Bb * NBLK * 64 * 64];
__device__ float g_S2[Bb * NBLK * 64 * 32];
__device__ float g_M2[Bb * 32 * Ee];

// ---------------- PTX helpers ----------------------------------------------
__device__ __forceinline__ uint32_t smem_u32(const void* p) {
    uint32_t a;
    asm("{ .reg .u64 t; cvta.to.shared.u64 t, %1; cvt.u32.u64 %0, t; }"
        : "=r"(a) : "l"(p));
    return a;
}
#define CP_ASYNC16(dst, src) \
    asm volatile("cp.async.cg.shared.global [%0], [%1], 16;" :: "r"(dst), "l"(src))
#define CP_COMMIT() asm volatile("cp.async.commit_group;" ::: "memory")
#define CP_WAIT1()  asm volatile("cp.async.wait_group 1;" ::: "memory")
#define CP_WAIT0()  asm volatile("cp.async.wait_group 0;" ::: "memory")

__device__ __forceinline__ void ldm_x4(uint32_t* r, uint32_t addr) {
    asm volatile("ldmatrix.sync.aligned.m8n8.x4.shared.b16 {%0,%1,%2,%3}, [%4];"
                 : "=r"(r[0]), "=r"(r[1]), "=r"(r[2]), "=r"(r[3]) : "r"(addr));
}
__device__ __forceinline__ void ldm_x4_trans(uint32_t* r, uint32_t addr) {
    asm volatile("ldmatrix.sync.aligned.m8n8.x4.trans.shared.b16 {%0,%1,%2,%3}, [%4];"
                 : "=r"(r[0]), "=r"(r[1]), "=r"(r[2]), "=r"(r[3]) : "r"(addr));
}
__device__ __forceinline__ void mma16816(float* c, const uint32_t* a, const uint32_t* b) {
    asm volatile("mma.sync.aligned.m16n8k16.row.col.f32.bf16.bf16.f32 "
                 "{%0,%1,%2,%3}, {%4,%5,%6,%7}, {%8,%9}, {%0,%1,%2,%3};"
                 : "+f"(c[0]), "+f"(c[1]), "+f"(c[2]), "+f"(c[3])
                 : "r"(a[0]), "r"(a[1]), "r"(a[2]), "r"(a[3]), "r"(b[0]), "r"(b[1]));
}

__device__ __forceinline__ void split_pair_store(
    float x, float y, __nv_bfloat16* hi, __nv_bfloat16* lo, size_t off)
{
    __nv_bfloat16 h0 = __float2bfloat16(x);
    __nv_bfloat16 h1 = __float2bfloat16(y);
    __nv_bfloat16 l0 = __float2bfloat16(x - __bfloat162float(h0));
    __nv_bfloat16 l1 = __float2bfloat16(y - __bfloat162float(h1));
    __nv_bfloat162 hh; hh.x = h0; hh.y = h1;
    __nv_bfloat162 ll; ll.x = l0; ll.y = l1;
    *(__nv_bfloat162*)(hi + off) = hh;
    *(__nv_bfloat162*)(lo + off) = ll;
}

// ---------------- split-bf16 NT GEMM (BK=32, 2-stage, 2 CTA/SM) ------------
#define ROWB 80
#define TILEB (128 * ROWB)
#define STAGEB (4 * TILEB)
#define GM_SMEM (2 * STAGEB)

__global__ __launch_bounds__(256, 2) void gemm_mma(
    const __nv_bfloat16* __restrict__ Ahi, const __nv_bfloat16* __restrict__ Alo,
    const __nv_bfloat16* __restrict__ Bhi, const __nv_bfloat16* __restrict__ Blo,
    const float* __restrict__ bias, float* __restrict__ C, int Kd, int Nout, int mode)
{
    extern __shared__ char smem[];
    const uint32_t sbase = smem_u32(smem);
    const int tid = threadIdx.x;
    const int wid = tid >> 5, lane = tid & 31;
    const int warp_m = wid & 3, warp_n = wid >> 2;
    const int m0 = blockIdx.y * 128, n0 = blockIdx.x * 128;

    const int r0 = tid >> 2;
    const int r1 = r0 + 64;
    const int c0 = (tid & 3) * 16;
    const int ce = (tid & 3) * 8;

    auto load_stage = [&](int s, int k0) {
        uint32_t dst = sbase + (s & 1) * STAGEB;
        const __nv_bfloat16* srcs[4] = {
            Ahi + (size_t)(m0 + r0) * Kd + k0 + ce,
            Alo + (size_t)(m0 + r0) * Kd + k0 + ce,
            Bhi + (size_t)(n0 + r0) * Kd + k0 + ce,
            Blo + (size_t)(n0 + r0) * Kd + k0 + ce };
#pragma unroll
        for (int t = 0; t < 4; t++) {
            uint32_t d = dst + t * TILEB;
            CP_ASYNC16(d + r0 * ROWB + c0, srcs[t]);
            CP_ASYNC16(d + r1 * ROWB + c0, srcs[t] + (size_t)64 * Kd);
        }
        CP_COMMIT();
    };

    float acc[2][8][4] = {};
    const int nstages = Kd >> 5;
    load_stage(0, 0);

    for (int s = 0; s < nstages; s++) {
        if (s + 1 < nstages) { load_stage(s + 1, (s + 1) << 5); CP_WAIT1(); }
        else                 { CP_WAIT0(); }
        __syncthreads();

        const uint32_t st = sbase + (s & 1) * STAGEB;
        const uint32_t sAh = st, sAl = st + TILEB, sBh = st + 2 * TILEB, sBl = st + 3 * TILEB;

        const uint32_t aRow = (uint32_t)(warp_m * 32 + (lane & 15)) * ROWB + ((lane >> 4) & 1) * 16;
        const int g = lane >> 3, lr = lane & 7;
        const uint32_t bRowBase = (uint32_t)(warp_n * 64 + ((g >> 1) & 1) * 8 + lr) * ROWB + (g & 1) * 16;

#pragma unroll
        for (int ks = 0; ks < 2; ks++) {
            uint32_t ah[2][4], al[2][4];
#pragma unroll
            for (int mt = 0; mt < 2; mt++) {
                uint32_t ao = aRow + (uint32_t)mt * 16 * ROWB + ks * 32;
                ldm_x4(ah[mt], sAh + ao);
                ldm_x4(al[mt], sAl + ao);
            }
#pragma unroll
            for (int p = 0; p < 4; p++) {
                uint32_t bo = bRowBase + (uint32_t)p * 16 * ROWB + ks * 32;
                uint32_t bh[4], bl[4];
                ldm_x4(bh, sBh + bo);
                ldm_x4(bl, sBl + bo);
#pragma unroll
                for (int mt = 0; mt < 2; mt++)
#pragma unroll
                    for (int j = 0; j < 2; j++) {
                        float* cc = acc[mt][2 * p + j];
                        mma16816(cc, ah[mt], &bh[j * 2]);
                        mma16816(cc, ah[mt], &bl[j * 2]);
                        mma16816(cc, al[mt], &bh[j * 2]);
                    }
            }
        }
        __syncthreads();
    }

    const int mrow = m0 + warp_m * 32 + (lane >> 2);
    const int ncol0 = n0 + warp_n * 64 + (lane & 3) * 2;
#pragma unroll
    for (int mt = 0; mt < 2; mt++)
#pragma unroll
        for (int nt = 0; nt < 8; nt++) {
            int m = mrow + mt * 16;
            int n = ncol0 + nt * 8;
            const float* cc = acc[mt][nt];
            if (mode == 1) {
                float2 bv = *(const float2*)(bias + n);
                float x0 = cc[0] + bv.x, y0 = cc[1] + bv.y;
                float x1 = cc[2] + bv.x, y1 = cc[3] + bv.y;
                if (n < 1024) {
                    split_pair_store(x0, y0, g_kqh, g_kql, (size_t)m * 1024 + n);
                    split_pair_store(x1, y1, g_kqh, g_kql, (size_t)(m + 8) * 1024 + n);
                } else {
                    float2 v0; v0.x = x0; v0.y = y0;
                    float2 v1; v1.x = x1; v1.y = y1;
                    *(float2*)(g_V + (size_t)m * Ee + (n - 1024)) = v0;
                    *(float2*)(g_V + (size_t)(m + 8) * Ee + (n - 1024)) = v1;
                }
            } else {  // mode 2: accumulate
                float2 o0 = *(float2*)(C + (size_t)m * Nout + n);
                float2 o1 = *(float2*)(C + (size_t)(m + 8) * Nout + n);
                o0.x += cc[0]; o0.y += cc[1];
                o1.x += cc[2]; o1.y += cc[3];
                *(float2*)(C + (size_t)m * Nout + n) = o0;
                *(float2*)(C + (size_t)(m + 8) * Nout + n) = o1;
            }
        }
}

// ---------------- prep kernels ---------------------------------------------
#define XN   (MROWS * Ee)
#define W3N  (3 * Ee * Ee)
#define WU1N (Ee * Ee)

__global__ void prep_x(const float* __restrict__ x)
{
    for (int i = blockIdx.x * blockDim.x + threadIdx.x; i < XN; i += gridDim.x * blockDim.x) {
        float v = x[i];
        __nv_bfloat16 h = __float2bfloat16(v);
        g_xhi[i] = h;
        g_xlo[i] = __float2bfloat16(v - __bfloat162float(h));
    }
}
__global__ void prep_w(const float* __restrict__ Wk, const float* __restrict__ Wq,
                       const float* __restrict__ Wv, const float* __restrict__ Wu)
{
    for (int i = blockIdx.x * blockDim.x + threadIdx.x; i < W3N + WU1N; i += gridDim.x * blockDim.x) {
        if (i < W3N) {
            int wsel = i >> 18;
            int off = i & 262143;
            const float* W = (wsel == 0) ? Wk : (wsel == 1) ? Wq : Wv;
            float v = W[off];
            __nv_bfloat16 h = __float2bfloat16(v);
            g_Whi[i] = h;
            g_Wlo[i] = __float2bfloat16(v - __bfloat162float(h));
        } else {
            int off = i - W3N;
            int n = off >> 9, c = off & 511;
            float v = Wu[(n << 10) + c];
            __nv_bfloat16 h = __float2bfloat16(v);
            g_Uhi[off] = h;
            g_Ulo[off] = __float2bfloat16(v - __bfloat162float(h));
        }
    }
}
__global__ void prep_bias(const float* __restrict__ bk, const float* __restrict__ bq,
                          const float* __restrict__ bv)
{
    int i = blockIdx.x * blockDim.x + threadIdx.x;
    if (i < Ee) {
        g_bias[i] = bk[i];
        g_bias[Ee + i] = bq[i];
        g_bias[2 * Ee + i] = bv[i];
    }
}

// ---------------- tensorized merged scores (R10 version) -------------------
#define HS_AROWS 64
#define HS_ATILE (HS_AROWS * ROWB)
#define HS_BTILE (128 * ROWB)
#define HS_STAGE (2 * HS_ATILE + 2 * HS_BTILE)
#define HS_SMEM (2 * HS_STAGE)

__global__ __launch_bounds__(256) void hs_score_mma()
{
    extern __shared__ char smem[];
    const uint32_t sbase = smem_u32(smem);
    const int blk = blockIdx.x, b = blockIdx.y;
    const int tid = threadIdx.x;
    const int wid = tid >> 5, lane = tid & 31;
    const int warp_m = wid & 3;
    const int warp_n = wid >> 2;
    const size_t rbase = (size_t)b * Tt + (size_t)blk * KBLK;

    auto load_stage = [&](int s, int k0) {
        uint32_t dst = sbase + (uint32_t)(s & 1) * HS_STAGE;
#pragma unroll
        for (int j = 0; j < 6; j++) {
            int f = tid + j * 256;
            if (f < 512) {
                const __nv_bfloat16* base = (f < 256) ? g_kqh : g_kql;
                int r = (f >> 2) & 63, c = f & 3;
                CP_ASYNC16(dst + ((f < 256) ? 0u : (uint32_t)HS_ATILE) + r * ROWB + c * 16,
                           base + (rbase + r) * 1024 + k0 + c * 8);
            } else {
                int fb = f - 512;
                const __nv_bfloat16* base = (fb < 512) ? g_kqh : g_kql;
                int r = (fb >> 2) & 127, c = fb & 3;
                size_t tok = (size_t)b * Tt +
                    ((r < 64) ? (size_t)(blk * KBLK + r) : (size_t)((r & 31) * KBLK));
                CP_ASYNC16(dst + 2 * HS_ATILE + ((fb < 512) ? 0u : (uint32_t)HS_BTILE)
                               + r * ROWB + c * 16,
                           base + tok * 1024 + 512 + k0 + c * 8);
            }
        }
        CP_COMMIT();
    };

    float acc[8][4] = {};
    const int nstages = Ee >> 5;
    load_stage(0, 0);

    const uint32_t aRow = (uint32_t)(warp_m * 16 + (lane & 15)) * ROWB + ((lane >> 4) & 1) * 16;
    const int g = lane >> 3, lr = lane & 7;
    const uint32_t bRowBase = (uint32_t)(warp_n * 64 + ((g >> 1) & 1) * 8 + lr) * ROWB + (g & 1) * 16;

    for (int s = 0; s < nstages; s++) {
        if (s + 1 < nstages) { load_stage(s + 1, (s + 1) << 5); CP_WAIT1(); }
        else                 { CP_WAIT0(); }
        __syncthreads();

        const uint32_t st = sbase + (uint32_t)(s & 1) * HS_STAGE;
        const uint32_t sAh = st, sAl = st + HS_ATILE;
        const uint32_t sBh = st + 2 * HS_ATILE, sBl = sBh + HS_BTILE;

#pragma unroll
        for (int ks = 0; ks < 2; ks++) {
            uint32_t ah[4], al[4];
            uint32_t ao = aRow + ks * 32;
            ldm_x4(ah, sAh + ao);
            ldm_x4(al, sAl + ao);
#pragma unroll
            for (int p = 0; p < 4; p++) {
                uint32_t bo = bRowBase + (uint32_t)p * 16 * ROWB + ks * 32;
                uint32_t bh[4], bl[4];
                ldm_x4(bh, sBh + bo);
                ldm_x4(bl, sBl + bo);
#pragma unroll
                for (int j = 0; j < 2; j++) {
                    float* cc = acc[2 * p + j];
                    mma16816(cc, ah, &bh[j * 2]);
                    mma16816(cc, ah, &bl[j * 2]);
                    mma16816(cc, al, &bh[j * 2]);
                }
            }
        }
        __syncthreads();
    }

    float* d1 = g_S1 + ((size_t)b * NBLK + blk) * 4096;
    float* d2 = g_S2 + ((size_t)b * NBLK + blk) * 2048;
    const int rr = warp_m * 16 + (lane >> 2);
    const int cc0 = warp_n * 64 + (lane & 3) * 2;
#pragma unroll
    for (int nt = 0; nt < 8; nt++) {
        int c = cc0 + nt * 8;
        const float* cc = acc[nt];
        if (c < 64) {
            float2 v0; v0.x = cc[0]; v0.y = cc[1];
            float2 v1; v1.x = cc[2]; v1.y = cc[3];
            *(float2*)(d1 + rr * 64 + c) = v0;
            *(float2*)(d1 + (rr + 8) * 64 + c) = v1;
        } else if (c < 96) {
            float2 v0; v0.x = cc[0]; v0.y = cc[1];
            float2 v1; v1.x = cc[2]; v1.y = cc[3];
            *(float2*)(d2 + rr * 32 + (c - 64)) = v0;
            *(float2*)(d2 + (rr + 8) * 32 + (c - 64)) = v1;
        }
    }
}

// ---------------- M2 = V_starts @ Wu2^T ------------------------------------
__global__ __launch_bounds__(256) void m2_kernel(const float* __restrict__ Wu)
{
    const int nc = blockIdx.x, b = blockIdx.y;
    const int tid = threadIdx.x;
    const int nl = tid & 63;
    const int quad = tid >> 6;

    __shared__ float Vs[32][64];
    __shared__ float Ws[64][64];

    float acc[8] = {};
    for (int e0 = 0; e0 < Ee; e0 += 64) {
        for (int f = tid; f < 512; f += 256) {
            int i = f >> 4, c4 = (f & 15) * 4;
            *(float4*)&Vs[i][c4] =
                *(const float4*)(g_V + ((size_t)b * Tt + (size_t)i * KBLK) * Ee + e0 + c4);
        }
        for (int f = tid; f < 1024; f += 256) {
            int n = f >> 4, c4 = (f & 15) * 4;
            float4 w = *(const float4*)(Wu + ((size_t)(nc * 64 + n) << 10) + 512 + e0 + c4);
            Ws[c4 + 0][n] = w.x; Ws[c4 + 1][n] = w.y;
            Ws[c4 + 2][n] = w.z; Ws[c4 + 3][n] = w.w;
        }
        __syncthreads();
#pragma unroll 8
        for (int e = 0; e < 64; e++) {
            float w = Ws[e][nl];
#pragma unroll
            for (int ii = 0; ii < 8; ii++)
                acc[ii] += Vs[quad * 8 + ii][e] * w;
        }
        __syncthreads();
    }
#pragma unroll
    for (int ii = 0; ii < 8; ii++)
        g_M2[((size_t)b * 32 + quad * 8 + ii) * Ee + nc * 64 + nl] = acc[ii];
}

// ---------------- out2: out = bu + masked(S2) @ M2 -------------------------
__global__ __launch_bounds__(256) void out2_kernel(const float* __restrict__ bu,
                                                   float* __restrict__ out)
{
    const int nc = blockIdx.x, rt = blockIdx.y, b = blockIdx.z;
    const int tid = threadIdx.x;
    const int ty = tid >> 4, tx = tid & 15;

    __shared__ float S2s[64][33];
    __shared__ float Ms[32][64];

    const float* sp = g_S2 + ((size_t)b * NBLK + rt) * 2048;
    for (int idx = tid; idx < 2048; idx += 256) {
        int r = idx >> 5, i = idx & 31;
        S2s[r][i] = sp[idx];
    }
    for (int idx = tid; idx < 2048; idx += 256) {
        int i = idx >> 6, n = idx & 63;
        Ms[i][n] = g_M2[((size_t)b * 32 + i) * Ee + nc * 64 + n];
    }
    __syncthreads();

    float acc[4][4] = {};
    for (int i = 0; i <= rt; i++) {
        float s_[4], m_[4];
#pragma unroll
        for (int u = 0; u < 4; u++) {
            s_[u] = S2s[ty * 4 + u][i];
            m_[u] = Ms[i][tx * 4 + u];
        }
#pragma unroll
        for (int u = 0; u < 4; u++)
#pragma unroll
            for (int v = 0; v < 4; v++)
                acc[u][v] += s_[u] * m_[v];
    }

    float4 bv = *(const float4*)(bu + nc * 64 + tx * 4);
    const size_t rowb = (size_t)b * Tt + (size_t)rt * KBLK;
#pragma unroll
    for (int u = 0; u < 4; u++) {
        float4 v;
        v.x = acc[u][0] + bv.x; v.y = acc[u][1] + bv.y;
        v.z = acc[u][2] + bv.z; v.w = acc[u][3] + bv.w;
        *(float4*)(out + (rowb + ty * 4 + u) * Ee + nc * 64 + tx * 4) = v;
    }
}

// ---------------- h1_out_mma: comb = mask(S1) @ V via mma + ldmatrix.trans -
// grid (NBLK, Bb, 4): per CTA 64 rows x 128 e-cols, K=64 (resident).
// smem: Sh/Sl 64x(128+16B pad), Vh/Vl 64x(256+16B pad) bf16.
#define SROW 144                         // 64 bf16 = 128 B + 16 pad
#define VROW 272                         // 128 bf16 = 256 B + 16 pad
#define H1_SMEM (2 * 64 * SROW + 2 * 64 * VROW)   // 18432 + 34816 = 53248

__global__ __launch_bounds__(256, 2) void h1_out_mma()
{
    extern __shared__ char smem[];
    const uint32_t sbase = smem_u32(smem);
    const int blk = blockIdx.x, b = blockIdx.y, ec = blockIdx.z;
    const int tid = threadIdx.x;
    const int wid = tid >> 5, lane = tid & 31;
    const int warp_m = wid & 3, warp_n = wid >> 2;
    const size_t rbase = (size_t)b * Tt + (size_t)blk * KBLK;
    const int e0 = ec * 128;

    char* sS = smem;                      // Sh then Sl
    char* sV = smem + 2 * 64 * SROW;      // Vh then Vl
    const uint32_t uSh = sbase, uSl = sbase + 64 * SROW;
    const uint32_t uVh = sbase + 2 * 64 * SROW, uVl = uVh + 64 * VROW;

    // fill S (mask + split); 2048 pair-slots
    {
        const float* sp = g_S1 + ((size_t)b * NBLK + blk) * 4096;
        for (int idx = tid; idx < 2048; idx += 256) {
            int r = idx >> 5, c2 = (idx & 31) * 2;
            float v0 = (c2 <= r) ? sp[r * 64 + c2] : 0.0f;
            float v1 = (c2 + 1 <= r) ? sp[r * 64 + c2 + 1] : 0.0f;
            __nv_bfloat16 h0 = __float2bfloat16(v0), h1 = __float2bfloat16(v1);
            __nv_bfloat162 hh; hh.x = h0; hh.y = h1;
            __nv_bfloat162 ll;
            ll.x = __float2bfloat16(v0 - __bfloat162float(h0));
            ll.y = __float2bfloat16(v1 - __bfloat162float(h1));
            *(__nv_bfloat162*)(sS + r * SROW + c2 * 2) = hh;
            *(__nv_bfloat162*)(sS + 64 * SROW + r * SROW + c2 * 2) = ll;
        }
    }
    // fill V (convert fp32 -> split bf16); rows = tokens, cols = 128 e
    {
        for (int f = tid; f < 2048; f += 256) {
            int r = f >> 5, q = (f & 31) * 4;
            float4 v = *(const float4*)(g_V + (rbase + r) * Ee + e0 + q);
            __nv_bfloat16 h0 = __float2bfloat16(v.x), h1 = __float2bfloat16(v.y);
            __nv_bfloat16 h2 = __float2bfloat16(v.z), h3 = __float2bfloat16(v.w);
            __nv_bfloat162 hA; hA.x = h0; hA.y = h1;
            __nv_bfloat162 hB; hB.x = h2; hB.y = h3;
            __nv_bfloat162 lA, lB;
            lA.x = __float2bfloat16(v.x - __bfloat162float(h0));
            lA.y = __float2bfloat16(v.y - __bfloat162float(h1));
            lB.x = __float2bfloat16(v.z - __bfloat162float(h2));
            lB.y = __float2bfloat16(v.w - __bfloat162float(h3));
            char* dh = sV + r * VROW + q * 2;
            char* dl = sV + 64 * VROW + r * VROW + q * 2;
            *(__nv_bfloat162*)(dh) = hA; *(__nv_bfloat162*)(dh + 4) = hB;
            *(__nv_bfloat162*)(dl) = lA; *(__nv_bfloat162*)(dl + 4) = lB;
        }
    }
    __syncthreads();

    // compute: warp tile 16 rows x 64 e;  K = 64 (4 ks steps)
    float acc[8][4] = {};
    const int g = lane >> 3, lr = lane & 7;
    const uint32_t aRow = (uint32_t)(warp_m * 16 + (lane & 15)) * SROW + ((lane >> 4) & 1) * 16;

#pragma unroll
    for (int ks = 0; ks < 4; ks++) {
        uint32_t ah[4], al[4];
        uint32_t ao = aRow + ks * 32;
        ldm_x4(ah, uSh + ao);
        ldm_x4(al, uSl + ao);
#pragma unroll
        for (int p = 0; p < 4; p++) {
            // B fragment via ldmatrix.trans from V[token][e]:
            // k = ks*16 + (g&1)*8 + lr ; n = warp_n*64 + p*16 + (g>>1)*8
            uint32_t bo = (uint32_t)(ks * 16 + (g & 1) * 8 + lr) * VROW
                        + (uint32_t)(warp_n * 64 + p * 16 + ((g >> 1) & 1) * 8) * 2;
            uint32_t bh[4], bl[4];
            ldm_x4_trans(bh, uVh + bo);
            ldm_x4_trans(bl, uVl + bo);
#pragma unroll
            for (int j = 0; j < 2; j++) {
                float* cc = acc[2 * p + j];
                mma16816(cc, ah, &bh[j * 2]);
                mma16816(cc, ah, &bl[j * 2]);
                mma16816(cc, al, &bh[j * 2]);
            }
        }
    }

    // epilogue: split bf16 comb
    const int rr = warp_m * 16 + (lane >> 2);
#pragma unroll
    for (int nt = 0; nt < 8; nt++) {
        int p = nt >> 1, j = nt & 1;
        int col = e0 + warp_n * 64 + p * 16 + j * 8 + (lane & 3) * 2;
        const float* cc = acc[nt];
        size_t row = rbase + rr;
        split_pair_store(cc[0], cc[1], g_chi, g_clo, row * Ee + col);
        split_pair_store(cc[2], cc[3], g_chi, g_clo, (row + 8) * Ee + col);
    }
}

// ---------------------------------------------------------------------------
extern "C" void kernel_launch(void* const* d_in, const int* in_sizes, int n_in,
                              void* d_out, int out_size)
{
    const float* x  = (const float*)d_in[0];
    const float* Wk = (const float*)d_in[1];
    const float* bk = (const float*)d_in[2];
    const float* Wq = (const float*)d_in[3];
    const float* bq = (const float*)d_in[4];
    const float* Wv = (const float*)d_in[5];
    const float* bv = (const float*)d_in[6];
    const float* Wu = (const float*)d_in[7];
    const float* bu = (const float*)d_in[8];
    float* out = (float*)d_out;

    float *pBias;
    __nv_bfloat16 *pxh, *pxl, *pWh, *pWl, *pUh, *pUl, *pch, *pcl;
    cudaGetSymbolAddress((void**)&pBias, g_bias);
    cudaGetSymbolAddress((void**)&pxh, g_xhi);
    cudaGetSymbolAddress((void**)&pxl, g_xlo);
    cudaGetSymbolAddress((void**)&pWh, g_Whi);
    cudaGetSymbolAddress((void**)&pWl, g_Wlo);
    cudaGetSymbolAddress((void**)&pUh, g_Uhi);
    cudaGetSymbolAddress((void**)&pUl, g_Ulo);
    cudaGetSymbolAddress((void**)&pch, g_chi);
    cudaGetSymbolAddress((void**)&pcl, g_clo);

    cudaFuncSetAttribute(gemm_mma, cudaFuncAttributeMaxDynamicSharedMemorySize, GM_SMEM);
    cudaFuncSetAttribute(hs_score_mma, cudaFuncAttributeMaxDynamicSharedMemorySize, HS_SMEM);
    cudaFuncSetAttribute(h1_out_mma, cudaFuncAttributeMaxDynamicSharedMemorySize, H1_SMEM);

    // launches 1-3: prep
    prep_x<<<1024, 256>>>(x);
    prep_w<<<640, 256>>>(Wk, Wq, Wv, Wu);
    prep_bias<<<2, 256>>>(bk, bq, bv);

    // launch 4: fused QKV projection (profiled)
    gemm_mma<<<dim3(NQKV / 128, MROWS / 128), 256, GM_SMEM>>>(
        pxh, pxl, pWh, pWl, pBias, nullptr, Ee, NQKV, 1);

    // launch 5: tensorized merged scores
    hs_score_mma<<<dim3(NBLK, Bb), 256, HS_SMEM>>>();

    // launch 6: M2 = V_starts @ Wu2^T
    m2_kernel<<<dim3(Ee / 64, Bb), 256>>>(Wu);

    // launch 7: h1 output via mma + ldmatrix.trans
    h1_out_mma<<<dim3(NBLK, Bb, 4), 256, H1_SMEM>>>();

    // launch 8: out = bu + masked(S2) @ M2
    out2_kernel<<<dim3(Ee / 64, NBLK, Bb), 256>>>(bu, out);

    // launch 9: out += h1 @ Wu1^T
    gemm_mma<<<dim3(Ee / 128, MROWS / 128), 256, GM_SMEM>>>(
        pch, pcl, pUh, pUl, pBias, out, Ee, Ee, 2);
}

// round 14
// speedup vs baseline: 1.0653x; 1.0547x over previous
#include <cuda_runtime.h>
#include <cuda_bf16.h>
#include <cstdint>

#define Bb 4
#define Tt 2048
#define Ee 512
#define KBLK 64
#define NBLK 32
#define MROWS (Bb * Tt)        // 8192
#define NQKV (3 * Ee)          // 1536
#define COMB2 544              // 512 (h1) + 32 (masked S2)

// ---------------- scratch (__device__ globals) ------------------------------
__device__ __nv_bfloat16 g_xhi[MROWS * Ee];
__device__ __nv_bfloat16 g_xlo[MROWS * Ee];
__device__ __nv_bfloat16 g_Whi[NQKV * Ee];
__device__ __nv_bfloat16 g_Wlo[NQKV * Ee];
__device__ __nv_bfloat16 g_Uhi[Ee * Ee];            // Wu1 split (stride 512)
__device__ __nv_bfloat16 g_Ulo[Ee * Ee];
__device__ __nv_bfloat16 g_chi[MROWS * COMB2];      // [h1 | maskedS2] split
__device__ __nv_bfloat16 g_clo[MROWS * COMB2];
__device__ __nv_bfloat16 g_kqh[MROWS * 1024];
__device__ __nv_bfloat16 g_kql[MROWS * 1024];
__device__ __nv_bfloat16 g_M2th[Bb * Ee * 32];      // M2^T split: [b][n][i]
__device__ __nv_bfloat16 g_M2tl[Bb * Ee * 32];
__device__ float g_V[MROWS * Ee];
__device__ float g_bias[NQKV];
__device__ float g_S1[Bb * NBLK * 64 * 64];

// ---------------- PTX helpers ----------------------------------------------
__device__ __forceinline__ uint32_t smem_u32(const void* p) {
    uint32_t a;
    asm("{ .reg .u64 t; cvta.to.shared.u64 t, %1; cvt.u32.u64 %0, t; }"
        : "=r"(a) : "l"(p));
    return a;
}
#define CP_ASYNC16(dst, src) \
    asm volatile("cp.async.cg.shared.global [%0], [%1], 16;" :: "r"(dst), "l"(src))
#define CP_COMMIT() asm volatile("cp.async.commit_group;" ::: "memory")
#define CP_WAIT1()  asm volatile("cp.async.wait_group 1;" ::: "memory")
#define CP_WAIT0()  asm volatile("cp.async.wait_group 0;" ::: "memory")

__device__ __forceinline__ void ldm_x4(uint32_t* r, uint32_t addr) {
    asm volatile("ldmatrix.sync.aligned.m8n8.x4.shared.b16 {%0,%1,%2,%3}, [%4];"
                 : "=r"(r[0]), "=r"(r[1]), "=r"(r[2]), "=r"(r[3]) : "r"(addr));
}
__device__ __forceinline__ void ldm_x4_trans(uint32_t* r, uint32_t addr) {
    asm volatile("ldmatrix.sync.aligned.m8n8.x4.trans.shared.b16 {%0,%1,%2,%3}, [%4];"
                 : "=r"(r[0]), "=r"(r[1]), "=r"(r[2]), "=r"(r[3]) : "r"(addr));
}
__device__ __forceinline__ void mma16816(float* c, const uint32_t* a, const uint32_t* b) {
    asm volatile("mma.sync.aligned.m16n8k16.row.col.f32.bf16.bf16.f32 "
                 "{%0,%1,%2,%3}, {%4,%5,%6,%7}, {%8,%9}, {%0,%1,%2,%3};"
                 : "+f"(c[0]), "+f"(c[1]), "+f"(c[2]), "+f"(c[3])
                 : "r"(a[0]), "r"(a[1]), "r"(a[2]), "r"(a[3]), "r"(b[0]), "r"(b[1]));
}

__device__ __forceinline__ void split_pair_store(
    float x, float y, __nv_bfloat16* hi, __nv_bfloat16* lo, size_t off)
{
    __nv_bfloat16 h0 = __float2bfloat16(x);
    __nv_bfloat16 h1 = __float2bfloat16(y);
    __nv_bfloat16 l0 = __float2bfloat16(x - __bfloat162float(h0));
    __nv_bfloat16 l1 = __float2bfloat16(y - __bfloat162float(h1));
    __nv_bfloat162 hh; hh.x = h0; hh.y = h1;
    __nv_bfloat162 ll; ll.x = l0; ll.y = l1;
    *(__nv_bfloat162*)(hi + off) = hh;
    *(__nv_bfloat162*)(lo + off) = ll;
}

// ---------------- split-bf16 NT GEMM (BK=32, 2-stage, 2 CTA/SM) ------------
// mode 1: QKV epilogue (n<1024 -> split bf16 K|Q ; n>=1024 -> fp32 V)
// mode 0: C = acc + bias.  B rows k<512 from Bhi/Blo (stride 512);
//         k>=512 from per-batch M2t (stride 32, batch = m0>>11).
#define ROWB 80
#define TILEB (128 * ROWB)
#define STAGEB (4 * TILEB)
#define GM_SMEM (2 * STAGEB)

__global__ __launch_bounds__(256, 2) void gemm_mma(
    const __nv_bfloat16* __restrict__ Ahi, const __nv_bfloat16* __restrict__ Alo,
    const __nv_bfloat16* __restrict__ Bhi, const __nv_bfloat16* __restrict__ Blo,
    const __nv_bfloat16* __restrict__ M2th, const __nv_bfloat16* __restrict__ M2tl,
    const float* __restrict__ bias, float* __restrict__ C, int Kd, int Nout, int mode)
{
    extern __shared__ char smem[];
    const uint32_t sbase = smem_u32(smem);
    const int tid = threadIdx.x;
    const int wid = tid >> 5, lane = tid & 31;
    const int warp_m = wid & 3, warp_n = wid >> 2;
    const int m0 = blockIdx.y * 128, n0 = blockIdx.x * 128;

    const int r0 = tid >> 2;
    const int r1 = r0 + 64;
    const int c0 = (tid & 3) * 16;
    const int ce = (tid & 3) * 8;

    auto load_stage = [&](int s, int k0) {
        uint32_t dst = sbase + (s & 1) * STAGEB;
        // A tiles (stride Kd)
        const __nv_bfloat16* a_h = Ahi + (size_t)(m0 + r0) * Kd + k0 + ce;
        const __nv_bfloat16* a_l = Alo + (size_t)(m0 + r0) * Kd + k0 + ce;
        CP_ASYNC16(dst + r0 * ROWB + c0, a_h);
        CP_ASYNC16(dst + r1 * ROWB + c0, a_h + (size_t)64 * Kd);
        CP_ASYNC16(dst + TILEB + r0 * ROWB + c0, a_l);
        CP_ASYNC16(dst + TILEB + r1 * ROWB + c0, a_l + (size_t)64 * Kd);
        // B tiles
        const __nv_bfloat16 *b_h, *b_l;
        size_t bstep;
        if (k0 < 512) {
            b_h = Bhi + (size_t)(n0 + r0) * 512 + k0 + ce;
            b_l = Blo + (size_t)(n0 + r0) * 512 + k0 + ce;
            bstep = (size_t)64 * 512;
        } else {
            size_t bb = (size_t)(m0 >> 11) * Ee;
            b_h = M2th + (bb + n0 + r0) * 32 + (k0 - 512) + ce;
            b_l = M2tl + (bb + n0 + r0) * 32 + (k0 - 512) + ce;
            bstep = (size_t)64 * 32;
        }
        CP_ASYNC16(dst + 2 * TILEB + r0 * ROWB + c0, b_h);
        CP_ASYNC16(dst + 2 * TILEB + r1 * ROWB + c0, b_h + bstep);
        CP_ASYNC16(dst + 3 * TILEB + r0 * ROWB + c0, b_l);
        CP_ASYNC16(dst + 3 * TILEB + r1 * ROWB + c0, b_l + bstep);
        CP_COMMIT();
    };

    float acc[2][8][4] = {};
    const int nstages = Kd >> 5;
    load_stage(0, 0);

    for (int s = 0; s < nstages; s++) {
        if (s + 1 < nstages) { load_stage(s + 1, (s + 1) << 5); CP_WAIT1(); }
        else                 { CP_WAIT0(); }
        __syncthreads();

        const uint32_t st = sbase + (s & 1) * STAGEB;
        const uint32_t sAh = st, sAl = st + TILEB, sBh = st + 2 * TILEB, sBl = st + 3 * TILEB;

        const uint32_t aRow = (uint32_t)(warp_m * 32 + (lane & 15)) * ROWB + ((lane >> 4) & 1) * 16;
        const int g = lane >> 3, lr = lane & 7;
        const uint32_t bRowBase = (uint32_t)(warp_n * 64 + ((g >> 1) & 1) * 8 + lr) * ROWB + (g & 1) * 16;

#pragma unroll
        for (int ks = 0; ks < 2; ks++) {
            uint32_t ah[2][4], al[2][4];
#pragma unroll
            for (int mt = 0; mt < 2; mt++) {
                uint32_t ao = aRow + (uint32_t)mt * 16 * ROWB + ks * 32;
                ldm_x4(ah[mt], sAh + ao);
                ldm_x4(al[mt], sAl + ao);
            }
#pragma unroll
            for (int p = 0; p < 4; p++) {
                uint32_t bo = bRowBase + (uint32_t)p * 16 * ROWB + ks * 32;
                uint32_t bh[4], bl[4];
                ldm_x4(bh, sBh + bo);
                ldm_x4(bl, sBl + bo);
#pragma unroll
                for (int mt = 0; mt < 2; mt++)
#pragma unroll
                    for (int j = 0; j < 2; j++) {
                        float* cc = acc[mt][2 * p + j];
                        mma16816(cc, ah[mt], &bh[j * 2]);
                        mma16816(cc, ah[mt], &bl[j * 2]);
                        mma16816(cc, al[mt], &bh[j * 2]);
                    }
            }
        }
        __syncthreads();
    }

    const int mrow = m0 + warp_m * 32 + (lane >> 2);
    const int ncol0 = n0 + warp_n * 64 + (lane & 3) * 2;
#pragma unroll
    for (int mt = 0; mt < 2; mt++)
#pragma unroll
        for (int nt = 0; nt < 8; nt++) {
            int m = mrow + mt * 16;
            int n = ncol0 + nt * 8;
            const float* cc = acc[mt][nt];
            float2 bv = *(const float2*)(bias + n);
            float x0 = cc[0] + bv.x, y0 = cc[1] + bv.y;
            float x1 = cc[2] + bv.x, y1 = cc[3] + bv.y;
            if (mode == 0) {
                float2 v0; v0.x = x0; v0.y = y0;
                float2 v1; v1.x = x1; v1.y = y1;
                *(float2*)(C + (size_t)m * Nout + n) = v0;
                *(float2*)(C + (size_t)(m + 8) * Nout + n) = v1;
            } else {
                if (n < 1024) {
                    split_pair_store(x0, y0, g_kqh, g_kql, (size_t)m * 1024 + n);
                    split_pair_store(x1, y1, g_kqh, g_kql, (size_t)(m + 8) * 1024 + n);
                } else {
                    float2 v0; v0.x = x0; v0.y = y0;
                    float2 v1; v1.x = x1; v1.y = y1;
                    *(float2*)(g_V + (size_t)m * Ee + (n - 1024)) = v0;
                    *(float2*)(g_V + (size_t)(m + 8) * Ee + (n - 1024)) = v1;
                }
            }
        }
}

// ---------------- fused prep ------------------------------------------------
#define XN   (MROWS * Ee)
#define W3N  (3 * Ee * Ee)
#define WU1N (Ee * Ee)
#define PTOT (XN + W3N + WU1N + NQKV)

__global__ void prep_kernel(const float* __restrict__ x,
                            const float* __restrict__ Wk, const float* __restrict__ Wq,
                            const float* __restrict__ Wv, const float* __restrict__ Wu,
                            const float* __restrict__ bk, const float* __restrict__ bq,
                            const float* __restrict__ bv)
{
    for (int i = blockIdx.x * blockDim.x + threadIdx.x; i < PTOT; i += gridDim.x * blockDim.x) {
        if (i < XN) {
            float v = x[i];
            __nv_bfloat16 h = __float2bfloat16(v);
            g_xhi[i] = h;
            g_xlo[i] = __float2bfloat16(v - __bfloat162float(h));
        } else if (i < XN + W3N) {
            int j = i - XN;
            int wsel = j >> 18;
            int off = j & 262143;
            const float* W = (wsel == 0) ? Wk : (wsel == 1) ? Wq : Wv;
            float v = W[off];
            __nv_bfloat16 h = __float2bfloat16(v);
            g_Whi[j] = h;
            g_Wlo[j] = __float2bfloat16(v - __bfloat162float(h));
        } else if (i < XN + W3N + WU1N) {
            int off = i - XN - W3N;
            int n = off >> 9, c = off & 511;
            float v = Wu[(n << 10) + c];
            __nv_bfloat16 h = __float2bfloat16(v);
            g_Uhi[off] = h;
            g_Ulo[off] = __float2bfloat16(v - __bfloat162float(h));
        } else {
            int off = i - XN - W3N - WU1N;
            g_bias[off] = (off < Ee) ? bk[off] : (off < 2 * Ee) ? bq[off - Ee] : bv[off - 2 * Ee];
        }
    }
}

// ---------------- tensorized merged scores ---------------------------------
// S1 -> fp32 buffer; S2 -> masked split-bf16 directly into comb cols 512..543
#define HS_AROWS 64
#define HS_ATILE (HS_AROWS * ROWB)
#define HS_BTILE (128 * ROWB)
#define HS_STAGE (2 * HS_ATILE + 2 * HS_BTILE)
#define HS_SMEM (2 * HS_STAGE)

__global__ __launch_bounds__(256) void hs_score_mma()
{
    extern __shared__ char smem[];
    const uint32_t sbase = smem_u32(smem);
    const int blk = blockIdx.x, b = blockIdx.y;
    const int tid = threadIdx.x;
    const int wid = tid >> 5, lane = tid & 31;
    const int warp_m = wid & 3;
    const int warp_n = wid >> 2;
    const size_t rbase = (size_t)b * Tt + (size_t)blk * KBLK;

    auto load_stage = [&](int s, int k0) {
        uint32_t dst = sbase + (uint32_t)(s & 1) * HS_STAGE;
#pragma unroll
        for (int j = 0; j < 6; j++) {
            int f = tid + j * 256;
            if (f < 512) {
                const __nv_bfloat16* base = (f < 256) ? g_kqh : g_kql;
                int r = (f >> 2) & 63, c = f & 3;
                CP_ASYNC16(dst + ((f < 256) ? 0u : (uint32_t)HS_ATILE) + r * ROWB + c * 16,
                           base + (rbase + r) * 1024 + k0 + c * 8);
            } else {
                int fb = f - 512;
                const __nv_bfloat16* base = (fb < 512) ? g_kqh : g_kql;
                int r = (fb >> 2) & 127, c = fb & 3;
                size_t tok = (size_t)b * Tt +
                    ((r < 64) ? (size_t)(blk * KBLK + r) : (size_t)((r & 31) * KBLK));
                CP_ASYNC16(dst + 2 * HS_ATILE + ((fb < 512) ? 0u : (uint32_t)HS_BTILE)
                               + r * ROWB + c * 16,
                           base + tok * 1024 + 512 + k0 + c * 8);
            }
        }
        CP_COMMIT();
    };

    float acc[8][4] = {};
    const int nstages = Ee >> 5;
    load_stage(0, 0);

    const uint32_t aRow = (uint32_t)(warp_m * 16 + (lane & 15)) * ROWB + ((lane >> 4) & 1) * 16;
    const int g = lane >> 3, lr = lane & 7;
    const uint32_t bRowBase = (uint32_t)(warp_n * 64 + ((g >> 1) & 1) * 8 + lr) * ROWB + (g & 1) * 16;

    for (int s = 0; s < nstages; s++) {
        if (s + 1 < nstages) { load_stage(s + 1, (s + 1) << 5); CP_WAIT1(); }
        else                 { CP_WAIT0(); }
        __syncthreads();

        const uint32_t st = sbase + (uint32_t)(s & 1) * HS_STAGE;
        const uint32_t sAh = st, sAl = st + HS_ATILE;
        const uint32_t sBh = st + 2 * HS_ATILE, sBl = sBh + HS_BTILE;

#pragma unroll
        for (int ks = 0; ks < 2; ks++) {
            uint32_t ah[4], al[4];
            uint32_t ao = aRow + ks * 32;
            ldm_x4(ah, sAh + ao);
            ldm_x4(al, sAl + ao);
#pragma unroll
            for (int p = 0; p < 4; p++) {
                uint32_t bo = bRowBase + (uint32_t)p * 16 * ROWB + ks * 32;
                uint32_t bh[4], bl[4];
                ldm_x4(bh, sBh + bo);
                ldm_x4(bl, sBl + bo);
#pragma unroll
                for (int j = 0; j < 2; j++) {
                    float* cc = acc[2 * p + j];
                    mma16816(cc, ah, &bh[j * 2]);
                    mma16816(cc, ah, &bl[j * 2]);
                    mma16816(cc, al, &bh[j * 2]);
                }
            }
        }
        __syncthreads();
    }

    float* d1 = g_S1 + ((size_t)b * NBLK + blk) * 4096;
    const int rr = warp_m * 16 + (lane >> 2);
    const int cc0 = warp_n * 64 + (lane & 3) * 2;
#pragma unroll
    for (int nt = 0; nt < 8; nt++) {
        int c = cc0 + nt * 8;
        const float* cc = acc[nt];
        if (c < 64) {
            float2 v0; v0.x = cc[0]; v0.y = cc[1];
            float2 v1; v1.x = cc[2]; v1.y = cc[3];
            *(float2*)(d1 + rr * 64 + c) = v0;
            *(float2*)(d1 + (rr + 8) * 64 + c) = v1;
        } else if (c < 96) {
            int i = c - 64;
            // mask i <= blk (block-causal), write split bf16 into comb[512+i]
            float a0 = (i     <= blk) ? cc[0] : 0.0f;
            float a1 = (i + 1 <= blk) ? cc[1] : 0.0f;
            float a2 = (i     <= blk) ? cc[2] : 0.0f;
            float a3 = (i + 1 <= blk) ? cc[3] : 0.0f;
            split_pair_store(a0, a1, g_chi, g_clo, (rbase + rr) * COMB2 + 512 + i);
            split_pair_store(a2, a3, g_chi, g_clo, (rbase + rr + 8) * COMB2 + 512 + i);
        }
    }
}

// ---------------- M2^T = (V_starts @ Wu2^T)^T, split bf16 ------------------
__global__ __launch_bounds__(256) void m2t_kernel(const float* __restrict__ Wu)
{
    const int nc = blockIdx.x, b = blockIdx.y;
    const int tid = threadIdx.x;
    const int nl = tid & 63;
    const int quad = tid >> 6;

    __shared__ float Vs[32][64];
    __shared__ float Ws[64][64];

    float acc[8] = {};
    for (int e0 = 0; e0 < Ee; e0 += 64) {
        for (int f = tid; f < 512; f += 256) {
            int i = f >> 4, c4 = (f & 15) * 4;
            *(float4*)&Vs[i][c4] =
                *(const float4*)(g_V + ((size_t)b * Tt + (size_t)i * KBLK) * Ee + e0 + c4);
        }
        for (int f = tid; f < 1024; f += 256) {
            int n = f >> 4, c4 = (f & 15) * 4;
            float4 w = *(const float4*)(Wu + ((size_t)(nc * 64 + n) << 10) + 512 + e0 + c4);
            Ws[c4 + 0][n] = w.x; Ws[c4 + 1][n] = w.y;
            Ws[c4 + 2][n] = w.z; Ws[c4 + 3][n] = w.w;
        }
        __syncthreads();
#pragma unroll 8
        for (int e = 0; e < 64; e++) {
            float w = Ws[e][nl];
#pragma unroll
            for (int ii = 0; ii < 8; ii++)
                acc[ii] += Vs[quad * 8 + ii][e] * w;
        }
        __syncthreads();
    }
    int n = nc * 64 + nl;
#pragma unroll
    for (int ii = 0; ii < 8; ii++) {
        int i = quad * 8 + ii;
        float v = acc[ii];
        __nv_bfloat16 h = __float2bfloat16(v);
        size_t off = ((size_t)b * Ee + n) * 32 + i;
        g_M2th[off] = h;
        g_M2tl[off] = __float2bfloat16(v - __bfloat162float(h));
    }
}

// ---------------- h1_out_mma: comb[0:512] = mask(S1) @ V -------------------
#define SROW 144
#define VROW 272
#define H1_SMEM (2 * 64 * SROW + 2 * 64 * VROW)

__global__ __launch_bounds__(256, 2) void h1_out_mma()
{
    extern __shared__ char smem[];
    const uint32_t sbase = smem_u32(smem);
    const int blk = blockIdx.x, b = blockIdx.y, ec = blockIdx.z;
    const int tid = threadIdx.x;
    const int wid = tid >> 5, lane = tid & 31;
    const int warp_m = wid & 3, warp_n = wid >> 2;
    const size_t rbase = (size_t)b * Tt + (size_t)blk * KBLK;
    const int e0 = ec * 128;

    char* sS = smem;
    char* sV = smem + 2 * 64 * SROW;
    const uint32_t uSh = sbase, uSl = sbase + 64 * SROW;
    const uint32_t uVh = sbase + 2 * 64 * SROW, uVl = uVh + 64 * VROW;

    {
        const float* sp = g_S1 + ((size_t)b * NBLK + blk) * 4096;
        for (int idx = tid; idx < 2048; idx += 256) {
            int r = idx >> 5, c2 = (idx & 31) * 2;
            float v0 = (c2 <= r) ? sp[r * 64 + c2] : 0.0f;
            float v1 = (c2 + 1 <= r) ? sp[r * 64 + c2 + 1] : 0.0f;
            __nv_bfloat16 h0 = __float2bfloat16(v0), h1 = __float2bfloat16(v1);
            __nv_bfloat162 hh; hh.x = h0; hh.y = h1;
            __nv_bfloat162 ll;
            ll.x = __float2bfloat16(v0 - __bfloat162float(h0));
            ll.y = __float2bfloat16(v1 - __bfloat162float(h1));
            *(__nv_bfloat162*)(sS + r * SROW + c2 * 2) = hh;
            *(__nv_bfloat162*)(sS + 64 * SROW + r * SROW + c2 * 2) = ll;
        }
    }
    {
        for (int f = tid; f < 2048; f += 256) {
            int r = f >> 5, q = (f & 31) * 4;
            float4 v = *(const float4*)(g_V + (rbase + r) * Ee + e0 + q);
            __nv_bfloat16 h0 = __float2bfloat16(v.x), h1 = __float2bfloat16(v.y);
            __nv_bfloat16 h2 = __float2bfloat16(v.z), h3 = __float2bfloat16(v.w);
            __nv_bfloat162 hA; hA.x = h0; hA.y = h1;
            __nv_bfloat162 hB; hB.x = h2; hB.y = h3;
            __nv_bfloat162 lA, lB;
            lA.x = __float2bfloat16(v.x - __bfloat162float(h0));
            lA.y = __float2bfloat16(v.y - __bfloat162float(h1));
            lB.x = __float2bfloat16(v.z - __bfloat162float(h2));
            lB.y = __float2bfloat16(v.w - __bfloat162float(h3));
            char* dh = sV + r * VROW + q * 2;
            char* dl = sV + 64 * VROW + r * VROW + q * 2;
            *(__nv_bfloat162*)(dh) = hA; *(__nv_bfloat162*)(dh + 4) = hB;
            *(__nv_bfloat162*)(dl) = lA; *(__nv_bfloat162*)(dl + 4) = lB;
        }
    }
    __syncthreads();

    float acc[8][4] = {};
    const int g = lane >> 3, lr = lane & 7;
    const uint32_t aRow = (uint32_t)(warp_m * 16 + (lane & 15)) * SROW + ((lane >> 4) & 1) * 16;

#pragma unroll
    for (int ks = 0; ks < 4; ks++) {
        uint32_t ah[4], al[4];
        uint32_t ao = aRow + ks * 32;
        ldm_x4(ah, uSh + ao);
        ldm_x4(al, uSl + ao);
#pragma unroll
        for (int p = 0; p < 4; p++) {
            uint32_t bo = (uint32_t)(ks * 16 + (g & 1) * 8 + lr) * VROW
                        + (uint32_t)(warp_n * 64 + p * 16 + ((g >> 1) & 1) * 8) * 2;
            uint32_t bh[4], bl[4];
            ldm_x4_trans(bh, uVh + bo);
            ldm_x4_trans(bl, uVl + bo);
#pragma unroll
            for (int j = 0; j < 2; j++) {
                float* cc = acc[2 * p + j];
                mma16816(cc, ah, &bh[j * 2]);
                mma16816(cc, ah, &bl[j * 2]);
                mma16816(cc, al, &bh[j * 2]);
            }
        }
    }

    const int rr = warp_m * 16 + (lane >> 2);
#pragma unroll
    for (int nt = 0; nt < 8; nt++) {
        int p = nt >> 1, j = nt & 1;
        int col = e0 + warp_n * 64 + p * 16 + j * 8 + (lane & 3) * 2;
        const float* cc = acc[nt];
        size_t row = rbase + rr;
        split_pair_store(cc[0], cc[1], g_chi, g_clo, row * COMB2 + col);
        split_pair_store(cc[2], cc[3], g_chi, g_clo, (row + 8) * COMB2 + col);
    }
}

// ---------------------------------------------------------------------------
extern "C" void kernel_launch(void* const* d_in, const int* in_sizes, int n_in,
                              void* d_out, int out_size)
{
    const float* x  = (const float*)d_in[0];
    const float* Wk = (const float*)d_in[1];
    const float* bk = (const float*)d_in[2];
    const float* Wq = (const float*)d_in[3];
    const float* bq = (const float*)d_in[4];
    const float* Wv = (const float*)d_in[5];
    const float* bv = (const float*)d_in[6];
    const float* Wu = (const float*)d_in[7];
    const float* bu = (const float*)d_in[8];
    float* out = (float*)d_out;

    float *pBias;
    __nv_bfloat16 *pxh, *pxl, *pWh, *pWl, *pUh, *pUl, *pch, *pcl, *pM2h, *pM2l;
    cudaGetSymbolAddress((void**)&pBias, g_bias);
    cudaGetSymbolAddress((void**)&pxh, g_xhi);
    cudaGetSymbolAddress((void**)&pxl, g_xlo);
    cudaGetSymbolAddress((void**)&pWh, g_Whi);
    cudaGetSymbolAddress((void**)&pWl, g_Wlo);
    cudaGetSymbolAddress((void**)&pUh, g_Uhi);
    cudaGetSymbolAddress((void**)&pUl, g_Ulo);
    cudaGetSymbolAddress((void**)&pch, g_chi);
    cudaGetSymbolAddress((void**)&pcl, g_clo);
    cudaGetSymbolAddress((void**)&pM2h, g_M2th);
    cudaGetSymbolAddress((void**)&pM2l, g_M2tl);

    cudaFuncSetAttribute(gemm_mma, cudaFuncAttributeMaxDynamicSharedMemorySize, GM_SMEM);
    cudaFuncSetAttribute(hs_score_mma, cudaFuncAttributeMaxDynamicSharedMemorySize, HS_SMEM);
    cudaFuncSetAttribute(h1_out_mma, cudaFuncAttributeMaxDynamicSharedMemorySize, H1_SMEM);

    // 1) fused prep
    prep_kernel<<<2048, 256>>>(x, Wk, Wq, Wv, Wu, bk, bq, bv);

    // 2) fused QKV projection -> split bf16 K|Q + fp32 V
    gemm_mma<<<dim3(NQKV / 128, MROWS / 128), 256, GM_SMEM>>>(
        pxh, pxl, pWh, pWl, nullptr, nullptr, pBias, nullptr, Ee, NQKV, 1);

    // 3) merged scores: S1 fp32 + masked S2 -> comb[512:544]
    hs_score_mma<<<dim3(NBLK, Bb), 256, HS_SMEM>>>();

    // 4) M2^T split bf16
    m2t_kernel<<<dim3(Ee / 64, Bb), 256>>>(Wu);

    // 5) h1 -> comb[0:512]
    h1_out_mma<<<dim3(NBLK, Bb, 4), 256, H1_SMEM>>>();

    // 6) out = comb @ [Wu1 | M2]^T + bu   (K = 544, last stage per-batch M2t)
    gemm_mma<<<dim3(Ee / 128, MROWS / 128), 256, GM_SMEM>>>(
        pch, pcl, pUh, pUl, pM2h, pM2l, bu, out, COMB2, Ee, 0);
}

// round 15
// speedup vs baseline: 1.1766x; 1.1045x over previous
#include <cuda_runtime.h>
#include <cuda_bf16.h>
#include <cstdint>

#define Bb 4
#define Tt 2048
#define Ee 512
#define KBLK 64
#define NBLK 32
#define MROWS (Bb * Tt)        // 8192
#define NQKV (3 * Ee)          // 1536
#define COMB2 544              // 512 (h1) + 32 (masked S2)

// ---------------- scratch (__device__ globals) ------------------------------
__device__ __nv_bfloat16 g_xhi[MROWS * Ee];
__device__ __nv_bfloat16 g_xlo[MROWS * Ee];
__device__ __nv_bfloat16 g_Whi[NQKV * Ee];
__device__ __nv_bfloat16 g_Wlo[NQKV * Ee];
__device__ __nv_bfloat16 g_Uhi[Ee * Ee];            // Wu1 split (stride 512)
__device__ __nv_bfloat16 g_Ulo[Ee * Ee];
__device__ __nv_bfloat16 g_chi[MROWS * COMB2];      // [h1 | maskedS2] split
__device__ __nv_bfloat16 g_clo[MROWS * COMB2];
__device__ __nv_bfloat16 g_kqh[MROWS * 1024];
__device__ __nv_bfloat16 g_kql[MROWS * 1024];
__device__ __nv_bfloat16 g_M2th[Bb * Ee * 32];      // M2^T split: [b][n][i]
__device__ __nv_bfloat16 g_M2tl[Bb * Ee * 32];
__device__ float g_M2p[8 * Bb * 32 * Ee];           // e-split partials (2 MB)
__device__ float g_V[MROWS * Ee];
__device__ float g_bias[NQKV];
__device__ float g_S1[Bb * NBLK * 64 * 64];

// ---------------- PTX helpers ----------------------------------------------
__device__ __forceinline__ uint32_t smem_u32(const void* p) {
    uint32_t a;
    asm("{ .reg .u64 t; cvta.to.shared.u64 t, %1; cvt.u32.u64 %0, t; }"
        : "=r"(a) : "l"(p));
    return a;
}
#define CP_ASYNC16(dst, src) \
    asm volatile("cp.async.cg.shared.global [%0], [%1], 16;" :: "r"(dst), "l"(src))
#define CP_COMMIT() asm volatile("cp.async.commit_group;" ::: "memory")
#define CP_WAIT1()  asm volatile("cp.async.wait_group 1;" ::: "memory")
#define CP_WAIT0()  asm volatile("cp.async.wait_group 0;" ::: "memory")

__device__ __forceinline__ void ldm_x4(uint32_t* r, uint32_t addr) {
    asm volatile("ldmatrix.sync.aligned.m8n8.x4.shared.b16 {%0,%1,%2,%3}, [%4];"
                 : "=r"(r[0]), "=r"(r[1]), "=r"(r[2]), "=r"(r[3]) : "r"(addr));
}
__device__ __forceinline__ void ldm_x4_trans(uint32_t* r, uint32_t addr) {
    asm volatile("ldmatrix.sync.aligned.m8n8.x4.trans.shared.b16 {%0,%1,%2,%3}, [%4];"
                 : "=r"(r[0]), "=r"(r[1]), "=r"(r[2]), "=r"(r[3]) : "r"(addr));
}
__device__ __forceinline__ void mma16816(float* c, const uint32_t* a, const uint32_t* b) {
    asm volatile("mma.sync.aligned.m16n8k16.row.col.f32.bf16.bf16.f32 "
                 "{%0,%1,%2,%3}, {%4,%5,%6,%7}, {%8,%9}, {%0,%1,%2,%3};"
                 : "+f"(c[0]), "+f"(c[1]), "+f"(c[2]), "+f"(c[3])
                 : "r"(a[0]), "r"(a[1]), "r"(a[2]), "r"(a[3]), "r"(b[0]), "r"(b[1]));
}

__device__ __forceinline__ void split_pair_store(
    float x, float y, __nv_bfloat16* hi, __nv_bfloat16* lo, size_t off)
{
    __nv_bfloat16 h0 = __float2bfloat16(x);
    __nv_bfloat16 h1 = __float2bfloat16(y);
    __nv_bfloat16 l0 = __float2bfloat16(x - __bfloat162float(h0));
    __nv_bfloat16 l1 = __float2bfloat16(y - __bfloat162float(h1));
    __nv_bfloat162 hh; hh.x = h0; hh.y = h1;
    __nv_bfloat162 ll; ll.x = l0; ll.y = l1;
    *(__nv_bfloat162*)(hi + off) = hh;
    *(__nv_bfloat162*)(lo + off) = ll;
}

// ---------------- split-bf16 NT GEMM (BK=32, 2-stage, 2 CTA/SM) ------------
#define ROWB 80
#define TILEB (128 * ROWB)
#define STAGEB (4 * TILEB)
#define GM_SMEM (2 * STAGEB)

__global__ __launch_bounds__(256, 2) void gemm_mma(
    const __nv_bfloat16* __restrict__ Ahi, const __nv_bfloat16* __restrict__ Alo,
    const __nv_bfloat16* __restrict__ Bhi, const __nv_bfloat16* __restrict__ Blo,
    const __nv_bfloat16* __restrict__ M2th, const __nv_bfloat16* __restrict__ M2tl,
    const float* __restrict__ bias, float* __restrict__ C, int Kd, int Nout, int mode)
{
    extern __shared__ char smem[];
    const uint32_t sbase = smem_u32(smem);
    const int tid = threadIdx.x;
    const int wid = tid >> 5, lane = tid & 31;
    const int warp_m = wid & 3, warp_n = wid >> 2;
    const int m0 = blockIdx.y * 128, n0 = blockIdx.x * 128;

    const int r0 = tid >> 2;
    const int r1 = r0 + 64;
    const int c0 = (tid & 3) * 16;
    const int ce = (tid & 3) * 8;

    auto load_stage = [&](int s, int k0) {
        uint32_t dst = sbase + (s & 1) * STAGEB;
        const __nv_bfloat16* a_h = Ahi + (size_t)(m0 + r0) * Kd + k0 + ce;
        const __nv_bfloat16* a_l = Alo + (size_t)(m0 + r0) * Kd + k0 + ce;
        CP_ASYNC16(dst + r0 * ROWB + c0, a_h);
        CP_ASYNC16(dst + r1 * ROWB + c0, a_h + (size_t)64 * Kd);
        CP_ASYNC16(dst + TILEB + r0 * ROWB + c0, a_l);
        CP_ASYNC16(dst + TILEB + r1 * ROWB + c0, a_l + (size_t)64 * Kd);
        const __nv_bfloat16 *b_h, *b_l;
        size_t bstep;
        if (k0 < 512) {
            b_h = Bhi + (size_t)(n0 + r0) * 512 + k0 + ce;
            b_l = Blo + (size_t)(n0 + r0) * 512 + k0 + ce;
            bstep = (size_t)64 * 512;
        } else {
            size_t bb = (size_t)(m0 >> 11) * Ee;
            b_h = M2th + (bb + n0 + r0) * 32 + (k0 - 512) + ce;
            b_l = M2tl + (bb + n0 + r0) * 32 + (k0 - 512) + ce;
            bstep = (size_t)64 * 32;
        }
        CP_ASYNC16(dst + 2 * TILEB + r0 * ROWB + c0, b_h);
        CP_ASYNC16(dst + 2 * TILEB + r1 * ROWB + c0, b_h + bstep);
        CP_ASYNC16(dst + 3 * TILEB + r0 * ROWB + c0, b_l);
        CP_ASYNC16(dst + 3 * TILEB + r1 * ROWB + c0, b_l + bstep);
        CP_COMMIT();
    };

    float acc[2][8][4] = {};
    const int nstages = Kd >> 5;
    load_stage(0, 0);

    for (int s = 0; s < nstages; s++) {
        if (s + 1 < nstages) { load_stage(s + 1, (s + 1) << 5); CP_WAIT1(); }
        else                 { CP_WAIT0(); }
        __syncthreads();

        const uint32_t st = sbase + (s & 1) * STAGEB;
        const uint32_t sAh = st, sAl = st + TILEB, sBh = st + 2 * TILEB, sBl = st + 3 * TILEB;

        const uint32_t aRow = (uint32_t)(warp_m * 32 + (lane & 15)) * ROWB + ((lane >> 4) & 1) * 16;
        const int g = lane >> 3, lr = lane & 7;
        const uint32_t bRowBase = (uint32_t)(warp_n * 64 + ((g >> 1) & 1) * 8 + lr) * ROWB + (g & 1) * 16;

#pragma unroll
        for (int ks = 0; ks < 2; ks++) {
            uint32_t ah[2][4], al[2][4];
#pragma unroll
            for (int mt = 0; mt < 2; mt++) {
                uint32_t ao = aRow + (uint32_t)mt * 16 * ROWB + ks * 32;
                ldm_x4(ah[mt], sAh + ao);
                ldm_x4(al[mt], sAl + ao);
            }
#pragma unroll
            for (int p = 0; p < 4; p++) {
                uint32_t bo = bRowBase + (uint32_t)p * 16 * ROWB + ks * 32;
                uint32_t bh[4], bl[4];
                ldm_x4(bh, sBh + bo);
                ldm_x4(bl, sBl + bo);
#pragma unroll
                for (int mt = 0; mt < 2; mt++)
#pragma unroll
                    for (int j = 0; j < 2; j++) {
                        float* cc = acc[mt][2 * p + j];
                        mma16816(cc, ah[mt], &bh[j * 2]);
                        mma16816(cc, ah[mt], &bl[j * 2]);
                        mma16816(cc, al[mt], &bh[j * 2]);
                    }
            }
        }
        __syncthreads();
    }

    const int mrow = m0 + warp_m * 32 + (lane >> 2);
    const int ncol0 = n0 + warp_n * 64 + (lane & 3) * 2;
#pragma unroll
    for (int mt = 0; mt < 2; mt++)
#pragma unroll
        for (int nt = 0; nt < 8; nt++) {
            int m = mrow + mt * 16;
            int n = ncol0 + nt * 8;
            const float* cc = acc[mt][nt];
            float2 bv = *(const float2*)(bias + n);
            float x0 = cc[0] + bv.x, y0 = cc[1] + bv.y;
            float x1 = cc[2] + bv.x, y1 = cc[3] + bv.y;
            if (mode == 0) {
                float2 v0; v0.x = x0; v0.y = y0;
                float2 v1; v1.x = x1; v1.y = y1;
                *(float2*)(C + (size_t)m * Nout + n) = v0;
                *(float2*)(C + (size_t)(m + 8) * Nout + n) = v1;
            } else {
                if (n < 1024) {
                    split_pair_store(x0, y0, g_kqh, g_kql, (size_t)m * 1024 + n);
                    split_pair_store(x1, y1, g_kqh, g_kql, (size_t)(m + 8) * 1024 + n);
                } else {
                    float2 v0; v0.x = x0; v0.y = y0;
                    float2 v1; v1.x = x1; v1.y = y1;
                    *(float2*)(g_V + (size_t)m * Ee + (n - 1024)) = v0;
                    *(float2*)(g_V + (size_t)(m + 8) * Ee + (n - 1024)) = v1;
                }
            }
        }
}

// ---------------- fused prep ------------------------------------------------
#define XN   (MROWS * Ee)
#define W3N  (3 * Ee * Ee)
#define WU1N (Ee * Ee)
#define PTOT (XN + W3N + WU1N + NQKV)

__global__ void prep_kernel(const float* __restrict__ x,
                            const float* __restrict__ Wk, const float* __restrict__ Wq,
                            const float* __restrict__ Wv, const float* __restrict__ Wu,
                            const float* __restrict__ bk, const float* __restrict__ bq,
                            const float* __restrict__ bv)
{
    for (int i = blockIdx.x * blockDim.x + threadIdx.x; i < PTOT; i += gridDim.x * blockDim.x) {
        if (i < XN) {
            float v = x[i];
            __nv_bfloat16 h = __float2bfloat16(v);
            g_xhi[i] = h;
            g_xlo[i] = __float2bfloat16(v - __bfloat162float(h));
        } else if (i < XN + W3N) {
            int j = i - XN;
            int wsel = j >> 18;
            int off = j & 262143;
            const float* W = (wsel == 0) ? Wk : (wsel == 1) ? Wq : Wv;
            float v = W[off];
            __nv_bfloat16 h = __float2bfloat16(v);
            g_Whi[j] = h;
            g_Wlo[j] = __float2bfloat16(v - __bfloat162float(h));
        } else if (i < XN + W3N + WU1N) {
            int off = i - XN - W3N;
            int n = off >> 9, c = off & 511;
            float v = Wu[(n << 10) + c];
            __nv_bfloat16 h = __float2bfloat16(v);
            g_Uhi[off] = h;
            g_Ulo[off] = __float2bfloat16(v - __bfloat162float(h));
        } else {
            int off = i - XN - W3N - WU1N;
            g_bias[off] = (off < Ee) ? bk[off] : (off < 2 * Ee) ? bq[off - Ee] : bv[off - 2 * Ee];
        }
    }
}

// ---------------- tensorized merged scores ---------------------------------
#define HS_AROWS 64
#define HS_ATILE (HS_AROWS * ROWB)
#define HS_BTILE (128 * ROWB)
#define HS_STAGE (2 * HS_ATILE + 2 * HS_BTILE)
#define HS_SMEM (2 * HS_STAGE)

__global__ __launch_bounds__(256) void hs_score_mma()
{
    extern __shared__ char smem[];
    const uint32_t sbase = smem_u32(smem);
    const int blk = blockIdx.x, b = blockIdx.y;
    const int tid = threadIdx.x;
    const int wid = tid >> 5, lane = tid & 31;
    const int warp_m = wid & 3;
    const int warp_n = wid >> 2;
    const size_t rbase = (size_t)b * Tt + (size_t)blk * KBLK;

    auto load_stage = [&](int s, int k0) {
        uint32_t dst = sbase + (uint32_t)(s & 1) * HS_STAGE;
#pragma unroll
        for (int j = 0; j < 6; j++) {
            int f = tid + j * 256;
            if (f < 512) {
                const __nv_bfloat16* base = (f < 256) ? g_kqh : g_kql;
                int r = (f >> 2) & 63, c = f & 3;
                CP_ASYNC16(dst + ((f < 256) ? 0u : (uint32_t)HS_ATILE) + r * ROWB + c * 16,
                           base + (rbase + r) * 1024 + k0 + c * 8);
            } else {
                int fb = f - 512;
                const __nv_bfloat16* base = (fb < 512) ? g_kqh : g_kql;
                int r = (fb >> 2) & 127, c = fb & 3;
                size_t tok = (size_t)b * Tt +
                    ((r < 64) ? (size_t)(blk * KBLK + r) : (size_t)((r & 31) * KBLK));
                CP_ASYNC16(dst + 2 * HS_ATILE + ((fb < 512) ? 0u : (uint32_t)HS_BTILE)
                               + r * ROWB + c * 16,
                           base + tok * 1024 + 512 + k0 + c * 8);
            }
        }
        CP_COMMIT();
    };

    float acc[8][4] = {};
    const int nstages = Ee >> 5;
    load_stage(0, 0);

    const uint32_t aRow = (uint32_t)(warp_m * 16 + (lane & 15)) * ROWB + ((lane >> 4) & 1) * 16;
    const int g = lane >> 3, lr = lane & 7;
    const uint32_t bRowBase = (uint32_t)(warp_n * 64 + ((g >> 1) & 1) * 8 + lr) * ROWB + (g & 1) * 16;

    for (int s = 0; s < nstages; s++) {
        if (s + 1 < nstages) { load_stage(s + 1, (s + 1) << 5); CP_WAIT1(); }
        else                 { CP_WAIT0(); }
        __syncthreads();

        const uint32_t st = sbase + (uint32_t)(s & 1) * HS_STAGE;
        const uint32_t sAh = st, sAl = st + HS_ATILE;
        const uint32_t sBh = st + 2 * HS_ATILE, sBl = sBh + HS_BTILE;

#pragma unroll
        for (int ks = 0; ks < 2; ks++) {
            uint32_t ah[4], al[4];
            uint32_t ao = aRow + ks * 32;
            ldm_x4(ah, sAh + ao);
            ldm_x4(al, sAl + ao);
#pragma unroll
            for (int p = 0; p < 4; p++) {
                uint32_t bo = bRowBase + (uint32_t)p * 16 * ROWB + ks * 32;
                uint32_t bh[4], bl[4];
                ldm_x4(bh, sBh + bo);
                ldm_x4(bl, sBl + bo);
#pragma unroll
                for (int j = 0; j < 2; j++) {
                    float* cc = acc[2 * p + j];
                    mma16816(cc, ah, &bh[j * 2]);
                    mma16816(cc, ah, &bl[j * 2]);
                    mma16816(cc, al, &bh[j * 2]);
                }
            }
        }
        __syncthreads();
    }

    float* d1 = g_S1 + ((size_t)b * NBLK + blk) * 4096;
    const int rr = warp_m * 16 + (lane >> 2);
    const int cc0 = warp_n * 64 + (lane & 3) * 2;
#pragma unroll
    for (int nt = 0; nt < 8; nt++) {
        int c = cc0 + nt * 8;
        const float* cc = acc[nt];
        if (c < 64) {
            float2 v0; v0.x = cc[0]; v0.y = cc[1];
            float2 v1; v1.x = cc[2]; v1.y = cc[3];
            *(float2*)(d1 + rr * 64 + c) = v0;
            *(float2*)(d1 + (rr + 8) * 64 + c) = v1;
        } else if (c < 96) {
            int i = c - 64;
            float a0 = (i     <= blk) ? cc[0] : 0.0f;
            float a1 = (i + 1 <= blk) ? cc[1] : 0.0f;
            float a2 = (i     <= blk) ? cc[2] : 0.0f;
            float a3 = (i + 1 <= blk) ? cc[3] : 0.0f;
            split_pair_store(a0, a1, g_chi, g_clo, (rbase + rr) * COMB2 + 512 + i);
            split_pair_store(a2, a3, g_chi, g_clo, (rbase + rr + 8) * COMB2 + 512 + i);
        }
    }
}

// ---------------- M2 partials: e-split 8x ----------------------------------
// grid (Ee/64, Bb, 8): each CTA one 64-e chunk -> g_M2p[ec][b][i][n]
__global__ __launch_bounds__(256) void m2t_part(const float* __restrict__ Wu)
{
    const int nc = blockIdx.x, b = blockIdx.y, ecb = blockIdx.z;
    const int tid = threadIdx.x;
    const int nl = tid & 63;
    const int quad = tid >> 6;
    const int e0 = ecb * 64;

    __shared__ float Vs[32][64];
    __shared__ float Ws[64][64];

    for (int f = tid; f < 512; f += 256) {
        int i = f >> 4, c4 = (f & 15) * 4;
        *(float4*)&Vs[i][c4] =
            *(const float4*)(g_V + ((size_t)b * Tt + (size_t)i * KBLK) * Ee + e0 + c4);
    }
    for (int f = tid; f < 1024; f += 256) {
        int n = f >> 4, c4 = (f & 15) * 4;
        float4 w = *(const float4*)(Wu + ((size_t)(nc * 64 + n) << 10) + 512 + e0 + c4);
        Ws[c4 + 0][n] = w.x; Ws[c4 + 1][n] = w.y;
        Ws[c4 + 2][n] = w.z; Ws[c4 + 3][n] = w.w;
    }
    __syncthreads();

    float acc[8] = {};
#pragma unroll 8
    for (int e = 0; e < 64; e++) {
        float w = Ws[e][nl];
#pragma unroll
        for (int ii = 0; ii < 8; ii++)
            acc[ii] += Vs[quad * 8 + ii][e] * w;
    }

    float* dst = g_M2p + (((size_t)ecb * Bb + b) * 32) * Ee + nc * 64 + nl;
#pragma unroll
    for (int ii = 0; ii < 8; ii++)
        dst[(size_t)(quad * 8 + ii) * Ee] = acc[ii];
}

// ---------------- M2 reduce + transpose + split ----------------------------
// total elems Bb*32*512 = 65536; 64 CTAs x 256 thr x 4 elems
__global__ __launch_bounds__(256) void m2t_reduce()
{
    const size_t stride = (size_t)Bb * 32 * Ee;   // per-partial
    int base = (blockIdx.x * 256 + threadIdx.x) * 4;
#pragma unroll
    for (int u = 0; u < 4; u++) {
        int idx = base + u;                       // [b][i][n]
        int b = idx >> 14;
        int i = (idx >> 9) & 31;
        int n = idx & 511;
        size_t po = ((size_t)b * 32 + i) * Ee + n;
        float s = 0.0f;
#pragma unroll
        for (int ec = 0; ec < 8; ec++)
            s += g_M2p[ec * stride + po];
        __nv_bfloat16 h = __float2bfloat16(s);
        size_t off = ((size_t)b * Ee + n) * 32 + i;   // transpose to [b][n][i]
        g_M2th[off] = h;
        g_M2tl[off] = __float2bfloat16(s - __bfloat162float(h));
    }
}

// ---------------- h1_out_mma: comb[0:512] = mask(S1) @ V -------------------
#define SROW 144
#define VROW 272
#define H1_SMEM (2 * 64 * SROW + 2 * 64 * VROW)

__global__ __launch_bounds__(256, 2) void h1_out_mma()
{
    extern __shared__ char smem[];
    const uint32_t sbase = smem_u32(smem);
    const int blk = blockIdx.x, b = blockIdx.y, ec = blockIdx.z;
    const int tid = threadIdx.x;
    const int wid = tid >> 5, lane = tid & 31;
    const int warp_m = wid & 3, warp_n = wid >> 2;
    const size_t rbase = (size_t)b * Tt + (size_t)blk * KBLK;
    const int e0 = ec * 128;

    char* sS = smem;
    char* sV = smem + 2 * 64 * SROW;
    const uint32_t uSh = sbase, uSl = sbase + 64 * SROW;
    const uint32_t uVh = sbase + 2 * 64 * SROW, uVl = uVh + 64 * VROW;

    {
        const float* sp = g_S1 + ((size_t)b * NBLK + blk) * 4096;
        for (int idx = tid; idx < 2048; idx += 256) {
            int r = idx >> 5, c2 = (idx & 31) * 2;
            float v0 = (c2 <= r) ? sp[r * 64 + c2] : 0.0f;
            float v1 = (c2 + 1 <= r) ? sp[r * 64 + c2 + 1] : 0.0f;
            __nv_bfloat16 h0 = __float2bfloat16(v0), h1 = __float2bfloat16(v1);
            __nv_bfloat162 hh; hh.x = h0; hh.y = h1;
            __nv_bfloat162 ll;
            ll.x = __float2bfloat16(v0 - __bfloat162float(h0));
            ll.y = __float2bfloat16(v1 - __bfloat162float(h1));
            *(__nv_bfloat162*)(sS + r * SROW + c2 * 2) = hh;
            *(__nv_bfloat162*)(sS + 64 * SROW + r * SROW + c2 * 2) = ll;
        }
    }
    {
        for (int f = tid; f < 2048; f += 256) {
            int r = f >> 5, q = (f & 31) * 4;
            float4 v = *(const float4*)(g_V + (rbase + r) * Ee + e0 + q);
            __nv_bfloat16 h0 = __float2bfloat16(v.x), h1 = __float2bfloat16(v.y);
            __nv_bfloat16 h2 = __float2bfloat16(v.z), h3 = __float2bfloat16(v.w);
            __nv_bfloat162 hA; hA.x = h0; hA.y = h1;
            __nv_bfloat162 hB; hB.x = h2; hB.y = h3;
            __nv_bfloat162 lA, lB;
            lA.x = __float2bfloat16(v.x - __bfloat162float(h0));
            lA.y = __float2bfloat16(v.y - __bfloat162float(h1));
            lB.x = __float2bfloat16(v.z - __bfloat162float(h2));
            lB.y = __float2bfloat16(v.w - __bfloat162float(h3));
            char* dh = sV + r * VROW + q * 2;
            char* dl = sV + 64 * VROW + r * VROW + q * 2;
            *(__nv_bfloat162*)(dh) = hA; *(__nv_bfloat162*)(dh + 4) = hB;
            *(__nv_bfloat162*)(dl) = lA; *(__nv_bfloat162*)(dl + 4) = lB;
        }
    }
    __syncthreads();

    float acc[8][4] = {};
    const int g = lane >> 3, lr = lane & 7;
    const uint32_t aRow = (uint32_t)(warp_m * 16 + (lane & 15)) * SROW + ((lane >> 4) & 1) * 16;

#pragma unroll
    for (int ks = 0; ks < 4; ks++) {
        uint32_t ah[4], al[4];
        uint32_t ao = aRow + ks * 32;
        ldm_x4(ah, uSh + ao);
        ldm_x4(al, uSl + ao);
#pragma unroll
        for (int p = 0; p < 4; p++) {
            uint32_t bo = (uint32_t)(ks * 16 + (g & 1) * 8 + lr) * VROW
                        + (uint32_t)(warp_n * 64 + p * 16 + ((g >> 1) & 1) * 8) * 2;
            uint32_t bh[4], bl[4];
            ldm_x4_trans(bh, uVh + bo);
            ldm_x4_trans(bl, uVl + bo);
#pragma unroll
            for (int j = 0; j < 2; j++) {
                float* cc = acc[2 * p + j];
                mma16816(cc, ah, &bh[j * 2]);
                mma16816(cc, ah, &bl[j * 2]);
                mma16816(cc, al, &bh[j * 2]);
            }
        }
    }

    const int rr = warp_m * 16 + (lane >> 2);
#pragma unroll
    for (int nt = 0; nt < 8; nt++) {
        int p = nt >> 1, j = nt & 1;
        int col = e0 + warp_n * 64 + p * 16 + j * 8 + (lane & 3) * 2;
        const float* cc = acc[nt];
        size_t row = rbase + rr;
        split_pair_store(cc[0], cc[1], g_chi, g_clo, row * COMB2 + col);
        split_pair_store(cc[2], cc[3], g_chi, g_clo, (row + 8) * COMB2 + col);
    }
}

// ---------------------------------------------------------------------------
extern "C" void kernel_launch(void* const* d_in, const int* in_sizes, int n_in,
                              void* d_out, int out_size)
{
    const float* x  = (const float*)d_in[0];
    const float* Wk = (const float*)d_in[1];
    const float* bk = (const float*)d_in[2];
    const float* Wq = (const float*)d_in[3];
    const float* bq = (const float*)d_in[4];
    const float* Wv = (const float*)d_in[5];
    const float* bv = (const float*)d_in[6];
    const float* Wu = (const float*)d_in[7];
    const float* bu = (const float*)d_in[8];
    float* out = (float*)d_out;

    float *pBias;
    __nv_bfloat16 *pxh, *pxl, *pWh, *pWl, *pUh, *pUl, *pch, *pcl, *pM2h, *pM2l;
    cudaGetSymbolAddress((void**)&pBias, g_bias);
    cudaGetSymbolAddress((void**)&pxh, g_xhi);
    cudaGetSymbolAddress((void**)&pxl, g_xlo);
    cudaGetSymbolAddress((void**)&pWh, g_Whi);
    cudaGetSymbolAddress((void**)&pWl, g_Wlo);
    cudaGetSymbolAddress((void**)&pUh, g_Uhi);
    cudaGetSymbolAddress((void**)&pUl, g_Ulo);
    cudaGetSymbolAddress((void**)&pch, g_chi);
    cudaGetSymbolAddress((void**)&pcl, g_clo);
    cudaGetSymbolAddress((void**)&pM2h, g_M2th);
    cudaGetSymbolAddress((void**)&pM2l, g_M2tl);

    cudaFuncSetAttribute(gemm_mma, cudaFuncAttributeMaxDynamicSharedMemorySize, GM_SMEM);
    cudaFuncSetAttribute(hs_score_mma, cudaFuncAttributeMaxDynamicSharedMemorySize, HS_SMEM);
    cudaFuncSetAttribute(h1_out_mma, cudaFuncAttributeMaxDynamicSharedMemorySize, H1_SMEM);

    // 1) fused prep
    prep_kernel<<<2048, 256>>>(x, Wk, Wq, Wv, Wu, bk, bq, bv);

    // 2) fused QKV projection -> split bf16 K|Q + fp32 V
    gemm_mma<<<dim3(NQKV / 128, MROWS / 128), 256, GM_SMEM>>>(
        pxh, pxl, pWh, pWl, nullptr, nullptr, pBias, nullptr, Ee, NQKV, 1);

    // 3-4) M2 chain (deps: g_V, Wu) — runs while scores kernel also queued
    m2t_part<<<dim3(Ee / 64, Bb, 8), 256>>>(Wu);
    m2t_reduce<<<64, 256>>>();

    // 5) merged scores: S1 fp32 + masked S2 -> comb[512:544]
    hs_score_mma<<<dim3(NBLK, Bb), 256, HS_SMEM>>>();

    // 6) h1 -> comb[0:512]
    h1_out_mma<<<dim3(NBLK, Bb, 4), 256, H1_SMEM>>>();

    // 7) out = comb @ [Wu1 | M2]^T + bu   (K = 544)
    gemm_mma<<<dim3(Ee / 128, MROWS / 128), 256, GM_SMEM>>>(
        pch, pcl, pUh, pUl, pM2h, pM2l, bu, out, COMB2, Ee, 0);
}

// round 16
// speedup vs baseline: 1.2069x; 1.0258x over previous
#include <cuda_runtime.h>
#include <cuda_bf16.h>
#include <cstdint>

#define Bb 4
#define Tt 2048
#define Ee 512
#define KBLK 64
#define NBLK 32
#define MROWS (Bb * Tt)        // 8192
#define NQKV (3 * Ee)          // 1536
#define COMB2 544              // 512 (h1) + 32 (masked S2)

// ---------------- scratch (__device__ globals) ------------------------------
__device__ __nv_bfloat16 g_xhi[MROWS * Ee];
__device__ __nv_bfloat16 g_xlo[MROWS * Ee];
__device__ __nv_bfloat16 g_Whi[NQKV * Ee];
__device__ __nv_bfloat16 g_Wlo[NQKV * Ee];
__device__ __nv_bfloat16 g_Uhi[Ee * Ee];            // Wu1 split (stride 512)
__device__ __nv_bfloat16 g_Ulo[Ee * Ee];
__device__ __nv_bfloat16 g_chi[MROWS * COMB2];      // [h1 | maskedS2] split
__device__ __nv_bfloat16 g_clo[MROWS * COMB2];
__device__ __nv_bfloat16 g_kqh[MROWS * 1024];
__device__ __nv_bfloat16 g_kql[MROWS * 1024];
__device__ __nv_bfloat16 g_M2th[Bb * Ee * 32];      // M2^T split: [b][n][i]
__device__ __nv_bfloat16 g_M2tl[Bb * Ee * 32];
__device__ float g_M2p[8 * Bb * 32 * Ee];           // e-split partials (2 MB)
__device__ float g_V[MROWS * Ee];
__device__ float g_bias[NQKV];

// ---------------- PTX helpers ----------------------------------------------
__device__ __forceinline__ uint32_t smem_u32(const void* p) {
    uint32_t a;
    asm("{ .reg .u64 t; cvta.to.shared.u64 t, %1; cvt.u32.u64 %0, t; }"
        : "=r"(a) : "l"(p));
    return a;
}
#define CP_ASYNC16(dst, src) \
    asm volatile("cp.async.cg.shared.global [%0], [%1], 16;" :: "r"(dst), "l"(src))
#define CP_COMMIT() asm volatile("cp.async.commit_group;" ::: "memory")
#define CP_WAIT1()  asm volatile("cp.async.wait_group 1;" ::: "memory")
#define CP_WAIT0()  asm volatile("cp.async.wait_group 0;" ::: "memory")

__device__ __forceinline__ void ldm_x4(uint32_t* r, uint32_t addr) {
    asm volatile("ldmatrix.sync.aligned.m8n8.x4.shared.b16 {%0,%1,%2,%3}, [%4];"
                 : "=r"(r[0]), "=r"(r[1]), "=r"(r[2]), "=r"(r[3]) : "r"(addr));
}
__device__ __forceinline__ void ldm_x4_trans(uint32_t* r, uint32_t addr) {
    asm volatile("ldmatrix.sync.aligned.m8n8.x4.trans.shared.b16 {%0,%1,%2,%3}, [%4];"
                 : "=r"(r[0]), "=r"(r[1]), "=r"(r[2]), "=r"(r[3]) : "r"(addr));
}
__device__ __forceinline__ void mma16816(float* c, const uint32_t* a, const uint32_t* b) {
    asm volatile("mma.sync.aligned.m16n8k16.row.col.f32.bf16.bf16.f32 "
                 "{%0,%1,%2,%3}, {%4,%5,%6,%7}, {%8,%9}, {%0,%1,%2,%3};"
                 : "+f"(c[0]), "+f"(c[1]), "+f"(c[2]), "+f"(c[3])
                 : "r"(a[0]), "r"(a[1]), "r"(a[2]), "r"(a[3]), "r"(b[0]), "r"(b[1]));
}

__device__ __forceinline__ void split_pair_store(
    float x, float y, __nv_bfloat16* hi, __nv_bfloat16* lo, size_t off)
{
    __nv_bfloat16 h0 = __float2bfloat16(x);
    __nv_bfloat16 h1 = __float2bfloat16(y);
    __nv_bfloat16 l0 = __float2bfloat16(x - __bfloat162float(h0));
    __nv_bfloat16 l1 = __float2bfloat16(y - __bfloat162float(h1));
    __nv_bfloat162 hh; hh.x = h0; hh.y = h1;
    __nv_bfloat162 ll; ll.x = l0; ll.y = l1;
    *(__nv_bfloat162*)(hi + off) = hh;
    *(__nv_bfloat162*)(lo + off) = ll;
}
__device__ __forceinline__ void split_pair_smem(
    float x, float y, char* hi, char* lo)
{
    __nv_bfloat16 h0 = __float2bfloat16(x);
    __nv_bfloat16 h1 = __float2bfloat16(y);
    __nv_bfloat162 hh; hh.x = h0; hh.y = h1;
    __nv_bfloat162 ll;
    ll.x = __float2bfloat16(x - __bfloat162float(h0));
    ll.y = __float2bfloat16(y - __bfloat162float(h1));
    *(__nv_bfloat162*)hi = hh;
    *(__nv_bfloat162*)lo = ll;
}

// ---------------- split-bf16 NT GEMM (BK=32, 2-stage, 2 CTA/SM) ------------
#define ROWB 80
#define TILEB (128 * ROWB)
#define STAGEB (4 * TILEB)
#define GM_SMEM (2 * STAGEB)

__global__ __launch_bounds__(256, 2) void gemm_mma(
    const __nv_bfloat16* __restrict__ Ahi, const __nv_bfloat16* __restrict__ Alo,
    const __nv_bfloat16* __restrict__ Bhi, const __nv_bfloat16* __restrict__ Blo,
    const __nv_bfloat16* __restrict__ M2th, const __nv_bfloat16* __restrict__ M2tl,
    const float* __restrict__ bias, float* __restrict__ C, int Kd, int Nout, int mode)
{
    extern __shared__ char smem[];
    const uint32_t sbase = smem_u32(smem);
    const int tid = threadIdx.x;
    const int wid = tid >> 5, lane = tid & 31;
    const int warp_m = wid & 3, warp_n = wid >> 2;
    const int m0 = blockIdx.y * 128, n0 = blockIdx.x * 128;

    const int r0 = tid >> 2;
    const int r1 = r0 + 64;
    const int c0 = (tid & 3) * 16;
    const int ce = (tid & 3) * 8;

    auto load_stage = [&](int s, int k0) {
        uint32_t dst = sbase + (s & 1) * STAGEB;
        const __nv_bfloat16* a_h = Ahi + (size_t)(m0 + r0) * Kd + k0 + ce;
        const __nv_bfloat16* a_l = Alo + (size_t)(m0 + r0) * Kd + k0 + ce;
        CP_ASYNC16(dst + r0 * ROWB + c0, a_h);
        CP_ASYNC16(dst + r1 * ROWB + c0, a_h + (size_t)64 * Kd);
        CP_ASYNC16(dst + TILEB + r0 * ROWB + c0, a_l);
        CP_ASYNC16(dst + TILEB + r1 * ROWB + c0, a_l + (size_t)64 * Kd);
        const __nv_bfloat16 *b_h, *b_l;
        size_t bstep;
        if (k0 < 512) {
            b_h = Bhi + (size_t)(n0 + r0) * 512 + k0 + ce;
            b_l = Blo + (size_t)(n0 + r0) * 512 + k0 + ce;
            bstep = (size_t)64 * 512;
        } else {
            size_t bb = (size_t)(m0 >> 11) * Ee;
            b_h = M2th + (bb + n0 + r0) * 32 + (k0 - 512) + ce;
            b_l = M2tl + (bb + n0 + r0) * 32 + (k0 - 512) + ce;
            bstep = (size_t)64 * 32;
        }
        CP_ASYNC16(dst + 2 * TILEB + r0 * ROWB + c0, b_h);
        CP_ASYNC16(dst + 2 * TILEB + r1 * ROWB + c0, b_h + bstep);
        CP_ASYNC16(dst + 3 * TILEB + r0 * ROWB + c0, b_l);
        CP_ASYNC16(dst + 3 * TILEB + r1 * ROWB + c0, b_l + bstep);
        CP_COMMIT();
    };

    float acc[2][8][4] = {};
    const int nstages = Kd >> 5;
    load_stage(0, 0);

    for (int s = 0; s < nstages; s++) {
        if (s + 1 < nstages) { load_stage(s + 1, (s + 1) << 5); CP_WAIT1(); }
        else                 { CP_WAIT0(); }
        __syncthreads();

        const uint32_t st = sbase + (s & 1) * STAGEB;
        const uint32_t sAh = st, sAl = st + TILEB, sBh = st + 2 * TILEB, sBl = st + 3 * TILEB;

        const uint32_t aRow = (uint32_t)(warp_m * 32 + (lane & 15)) * ROWB + ((lane >> 4) & 1) * 16;
        const int g = lane >> 3, lr = lane & 7;
        const uint32_t bRowBase = (uint32_t)(warp_n * 64 + ((g >> 1) & 1) * 8 + lr) * ROWB + (g & 1) * 16;

#pragma unroll
        for (int ks = 0; ks < 2; ks++) {
            uint32_t ah[2][4], al[2][4];
#pragma unroll
            for (int mt = 0; mt < 2; mt++) {
                uint32_t ao = aRow + (uint32_t)mt * 16 * ROWB + ks * 32;
                ldm_x4(ah[mt], sAh + ao);
                ldm_x4(al[mt], sAl + ao);
            }
#pragma unroll
            for (int p = 0; p < 4; p++) {
                uint32_t bo = bRowBase + (uint32_t)p * 16 * ROWB + ks * 32;
                uint32_t bh[4], bl[4];
                ldm_x4(bh, sBh + bo);
                ldm_x4(bl, sBl + bo);
#pragma unroll
                for (int mt = 0; mt < 2; mt++)
#pragma unroll
                    for (int j = 0; j < 2; j++) {
                        float* cc = acc[mt][2 * p + j];
                        mma16816(cc, ah[mt], &bh[j * 2]);
                        mma16816(cc, ah[mt], &bl[j * 2]);
                        mma16816(cc, al[mt], &bh[j * 2]);
                    }
            }
        }
        __syncthreads();
    }

    const int mrow = m0 + warp_m * 32 + (lane >> 2);
    const int ncol0 = n0 + warp_n * 64 + (lane & 3) * 2;
#pragma unroll
    for (int mt = 0; mt < 2; mt++)
#pragma unroll
        for (int nt = 0; nt < 8; nt++) {
            int m = mrow + mt * 16;
            int n = ncol0 + nt * 8;
            const float* cc = acc[mt][nt];
            float2 bv = *(const float2*)(bias + n);
            float x0 = cc[0] + bv.x, y0 = cc[1] + bv.y;
            float x1 = cc[2] + bv.x, y1 = cc[3] + bv.y;
            if (mode == 0) {
                float2 v0; v0.x = x0; v0.y = y0;
                float2 v1; v1.x = x1; v1.y = y1;
                *(float2*)(C + (size_t)m * Nout + n) = v0;
                *(float2*)(C + (size_t)(m + 8) * Nout + n) = v1;
            } else {
                if (n < 1024) {
                    split_pair_store(x0, y0, g_kqh, g_kql, (size_t)m * 1024 + n);
                    split_pair_store(x1, y1, g_kqh, g_kql, (size_t)(m + 8) * 1024 + n);
                } else {
                    float2 v0; v0.x = x0; v0.y = y0;
                    float2 v1; v1.x = x1; v1.y = y1;
                    *(float2*)(g_V + (size_t)m * Ee + (n - 1024)) = v0;
                    *(float2*)(g_V + (size_t)(m + 8) * Ee + (n - 1024)) = v1;
                }
            }
        }
}

// ---------------- fused prep ------------------------------------------------
#define XN   (MROWS * Ee)
#define W3N  (3 * Ee * Ee)
#define WU1N (Ee * Ee)
#define PTOT (XN + W3N + WU1N + NQKV)

__global__ void prep_kernel(const float* __restrict__ x,
                            const float* __restrict__ Wk, const float* __restrict__ Wq,
                            const float* __restrict__ Wv, const float* __restrict__ Wu,
                            const float* __restrict__ bk, const float* __restrict__ bq,
                            const float* __restrict__ bv)
{
    for (int i = blockIdx.x * blockDim.x + threadIdx.x; i < PTOT; i += gridDim.x * blockDim.x) {
        if (i < XN) {
            float v = x[i];
            __nv_bfloat16 h = __float2bfloat16(v);
            g_xhi[i] = h;
            g_xlo[i] = __float2bfloat16(v - __bfloat162float(h));
        } else if (i < XN + W3N) {
            int j = i - XN;
            int wsel = j >> 18;
            int off = j & 262143;
            const float* W = (wsel == 0) ? Wk : (wsel == 1) ? Wq : Wv;
            float v = W[off];
            __nv_bfloat16 h = __float2bfloat16(v);
            g_Whi[j] = h;
            g_Wlo[j] = __float2bfloat16(v - __bfloat162float(h));
        } else if (i < XN + W3N + WU1N) {
            int off = i - XN - W3N;
            int n = off >> 9, c = off & 511;
            float v = Wu[(n << 10) + c];
            __nv_bfloat16 h = __float2bfloat16(v);
            g_Uhi[off] = h;
            g_Ulo[off] = __float2bfloat16(v - __bfloat162float(h));
        } else {
            int off = i - XN - W3N - WU1N;
            g_bias[off] = (off < Ee) ? bk[off] : (off < 2 * Ee) ? bq[off - Ee] : bv[off - 2 * Ee];
        }
    }
}

// ---------------- fused scores + h1 output ---------------------------------
// Phase 1: S[64x128] = K_blk . [Q_blk | Q_starts | dup]^T  (16 k-stages)
//   - S2 (cols 64..95) masked -> comb[512:544]
//   - S1 (cols 0..63) masked+split -> smem
// Phase 2: comb[0:512] = S1 @ V (4 e-chunks of 128, ldmatrix.trans B)
#define HS_AROWS 64
#define HS_ATILE (HS_AROWS * ROWB)          // 5120
#define HS_BTILE (128 * ROWB)               // 10240
#define HS_STAGE (2 * HS_ATILE + 2 * HS_BTILE)   // 30720
#define HS_SMEM (2 * HS_STAGE)              // 61440
#define SROW 144                            // S phase-2 row stride
#define VROW 272                            // V phase-2 row stride (128 bf16 + pad)
// phase-2 layout: Sh(0) Sl(+64*SROW) Vh(+2*64*SROW) Vl(+...+64*VROW) = 53248 <= 61440

__global__ __launch_bounds__(256) void hs_h1_fused()
{
    extern __shared__ char smem[];
    const uint32_t sbase = smem_u32(smem);
    const int blk = blockIdx.x, b = blockIdx.y;
    const int tid = threadIdx.x;
    const int wid = tid >> 5, lane = tid & 31;
    const int warp_m = wid & 3;
    const int warp_n = wid >> 2;
    const size_t rbase = (size_t)b * Tt + (size_t)blk * KBLK;

    auto load_stage = [&](int s, int k0) {
        uint32_t dst = sbase + (uint32_t)(s & 1) * HS_STAGE;
#pragma unroll
        for (int j = 0; j < 6; j++) {
            int f = tid + j * 256;
            if (f < 512) {
                const __nv_bfloat16* base = (f < 256) ? g_kqh : g_kql;
                int r = (f >> 2) & 63, c = f & 3;
                CP_ASYNC16(dst + ((f < 256) ? 0u : (uint32_t)HS_ATILE) + r * ROWB + c * 16,
                           base + (rbase + r) * 1024 + k0 + c * 8);
            } else {
                int fb = f - 512;
                const __nv_bfloat16* base = (fb < 512) ? g_kqh : g_kql;
                int r = (fb >> 2) & 127, c = fb & 3;
                size_t tok = (size_t)b * Tt +
                    ((r < 64) ? (size_t)(blk * KBLK + r) : (size_t)((r & 31) * KBLK));
                CP_ASYNC16(dst + 2 * HS_ATILE + ((fb < 512) ? 0u : (uint32_t)HS_BTILE)
                               + r * ROWB + c * 16,
                           base + tok * 1024 + 512 + k0 + c * 8);
            }
        }
        CP_COMMIT();
    };

    float acc[8][4] = {};
    const int nstages = Ee >> 5;
    load_stage(0, 0);

    const uint32_t aRowP1 = (uint32_t)(warp_m * 16 + (lane & 15)) * ROWB + ((lane >> 4) & 1) * 16;
    const int g = lane >> 3, lr = lane & 7;
    const uint32_t bRowBase = (uint32_t)(warp_n * 64 + ((g >> 1) & 1) * 8 + lr) * ROWB + (g & 1) * 16;

    for (int s = 0; s < nstages; s++) {
        if (s + 1 < nstages) { load_stage(s + 1, (s + 1) << 5); CP_WAIT1(); }
        else                 { CP_WAIT0(); }
        __syncthreads();

        const uint32_t st = sbase + (uint32_t)(s & 1) * HS_STAGE;
        const uint32_t sAh = st, sAl = st + HS_ATILE;
        const uint32_t sBh = st + 2 * HS_ATILE, sBl = sBh + HS_BTILE;

#pragma unroll
        for (int ks = 0; ks < 2; ks++) {
            uint32_t ah[4], al[4];
            uint32_t ao = aRowP1 + ks * 32;
            ldm_x4(ah, sAh + ao);
            ldm_x4(al, sAl + ao);
#pragma unroll
            for (int p = 0; p < 4; p++) {
                uint32_t bo = bRowBase + (uint32_t)p * 16 * ROWB + ks * 32;
                uint32_t bh[4], bl[4];
                ldm_x4(bh, sBh + bo);
                ldm_x4(bl, sBl + bo);
#pragma unroll
                for (int j = 0; j < 2; j++) {
                    float* cc = acc[2 * p + j];
                    mma16816(cc, ah, &bh[j * 2]);
                    mma16816(cc, ah, &bl[j * 2]);
                    mma16816(cc, al, &bh[j * 2]);
                }
            }
        }
        __syncthreads();
    }
    __syncthreads();   // staging buffers now free for S

    // Phase-1 epilogue: S2 -> comb[512:544]; S1 masked+split -> smem
    char* sS = smem;
    const int rr = warp_m * 16 + (lane >> 2);
    const int cc0 = warp_n * 64 + (lane & 3) * 2;
#pragma unroll
    for (int nt = 0; nt < 8; nt++) {
        int c = cc0 + nt * 8;
        const float* cc = acc[nt];
        if (c < 64) {
            float a0 = (c     <= rr) ? cc[0] : 0.0f;
            float a1 = (c + 1 <= rr) ? cc[1] : 0.0f;
            float a2 = (c     <= rr + 8) ? cc[2] : 0.0f;
            float a3 = (c + 1 <= rr + 8) ? cc[3] : 0.0f;
            split_pair_smem(a0, a1, sS + rr * SROW + c * 2,
                                   sS + 64 * SROW + rr * SROW + c * 2);
            split_pair_smem(a2, a3, sS + (rr + 8) * SROW + c * 2,
                                   sS + 64 * SROW + (rr + 8) * SROW + c * 2);
        } else if (c < 96) {
            int i = c - 64;
            float a0 = (i     <= blk) ? cc[0] : 0.0f;
            float a1 = (i + 1 <= blk) ? cc[1] : 0.0f;
            float a2 = (i     <= blk) ? cc[2] : 0.0f;
            float a3 = (i + 1 <= blk) ? cc[3] : 0.0f;
            split_pair_store(a0, a1, g_chi, g_clo, (rbase + rr) * COMB2 + 512 + i);
            split_pair_store(a2, a3, g_chi, g_clo, (rbase + rr + 8) * COMB2 + 512 + i);
        }
    }
    __syncthreads();

    // Phase 2: comb[0:512] = S1 @ V, 4 chunks of 128 e
    char* sV = smem + 2 * 64 * SROW;
    const uint32_t uSh = sbase, uSl = sbase + 64 * SROW;
    const uint32_t uVh = sbase + 2 * 64 * SROW, uVl = uVh + 64 * VROW;
    const uint32_t aRowP2 = (uint32_t)(warp_m * 16 + (lane & 15)) * SROW + ((lane >> 4) & 1) * 16;

    for (int ec = 0; ec < 4; ec++) {
        const int e0 = ec * 128;
        for (int f = tid; f < 2048; f += 256) {
            int r = f >> 5, q = (f & 31) * 4;
            float4 v = *(const float4*)(g_V + (rbase + r) * Ee + e0 + q);
            __nv_bfloat16 h0 = __float2bfloat16(v.x), h1 = __float2bfloat16(v.y);
            __nv_bfloat16 h2 = __float2bfloat16(v.z), h3 = __float2bfloat16(v.w);
            __nv_bfloat162 hA; hA.x = h0; hA.y = h1;
            __nv_bfloat162 hB; hB.x = h2; hB.y = h3;
            __nv_bfloat162 lA, lB;
            lA.x = __float2bfloat16(v.x - __bfloat162float(h0));
            lA.y = __float2bfloat16(v.y - __bfloat162float(h1));
            lB.x = __float2bfloat16(v.z - __bfloat162float(h2));
            lB.y = __float2bfloat16(v.w - __bfloat162float(h3));
            char* dh = sV + r * VROW + q * 2;
            char* dl = sV + 64 * VROW + r * VROW + q * 2;
            *(__nv_bfloat162*)(dh) = hA; *(__nv_bfloat162*)(dh + 4) = hB;
            *(__nv_bfloat162*)(dl) = lA; *(__nv_bfloat162*)(dl + 4) = lB;
        }
        __syncthreads();

        float o[8][4] = {};
#pragma unroll
        for (int ks = 0; ks < 4; ks++) {
            uint32_t ah[4], al[4];
            uint32_t ao = aRowP2 + ks * 32;
            ldm_x4(ah, uSh + ao);
            ldm_x4(al, uSl + ao);
#pragma unroll
            for (int p = 0; p < 4; p++) {
                uint32_t bo = (uint32_t)(ks * 16 + (g & 1) * 8 + lr) * VROW
                            + (uint32_t)(warp_n * 64 + p * 16 + ((g >> 1) & 1) * 8) * 2;
                uint32_t bh[4], bl[4];
                ldm_x4_trans(bh, uVh + bo);
                ldm_x4_trans(bl, uVl + bo);
#pragma unroll
                for (int j = 0; j < 2; j++) {
                    float* cc = o[2 * p + j];
                    mma16816(cc, ah, &bh[j * 2]);
                    mma16816(cc, ah, &bl[j * 2]);
                    mma16816(cc, al, &bh[j * 2]);
                }
            }
        }

#pragma unroll
        for (int nt = 0; nt < 8; nt++) {
            int p = nt >> 1, j = nt & 1;
            int col = e0 + warp_n * 64 + p * 16 + j * 8 + (lane & 3) * 2;
            const float* cc = o[nt];
            size_t row = rbase + rr;
            split_pair_store(cc[0], cc[1], g_chi, g_clo, row * COMB2 + col);
            split_pair_store(cc[2], cc[3], g_chi, g_clo, (row + 8) * COMB2 + col);
        }
        __syncthreads();
    }
}

// ---------------- M2 partials: e-split 8x ----------------------------------
__global__ __launch_bounds__(256) void m2t_part(const float* __restrict__ Wu)
{
    const int nc = blockIdx.x, b = blockIdx.y, ecb = blockIdx.z;
    const int tid = threadIdx.x;
    const int nl = tid & 63;
    const int quad = tid >> 6;
    const int e0 = ecb * 64;

    __shared__ float Vs[32][64];
    __shared__ float Ws[64][64];

    for (int f = tid; f < 512; f += 256) {
        int i = f >> 4, c4 = (f & 15) * 4;
        *(float4*)&Vs[i][c4] =
            *(const float4*)(g_V + ((size_t)b * Tt + (size_t)i * KBLK) * Ee + e0 + c4);
    }
    for (int f = tid; f < 1024; f += 256) {
        int n = f >> 4, c4 = (f & 15) * 4;
        float4 w = *(const float4*)(Wu + ((size_t)(nc * 64 + n) << 10) + 512 + e0 + c4);
        Ws[c4 + 0][n] = w.x; Ws[c4 + 1][n] = w.y;
        Ws[c4 + 2][n] = w.z; Ws[c4 + 3][n] = w.w;
    }
    __syncthreads();

    float acc[8] = {};
#pragma unroll 8
    for (int e = 0; e < 64; e++) {
        float w = Ws[e][nl];
#pragma unroll
        for (int ii = 0; ii < 8; ii++)
            acc[ii] += Vs[quad * 8 + ii][e] * w;
    }

    float* dst = g_M2p + (((size_t)ecb * Bb + b) * 32) * Ee + nc * 64 + nl;
#pragma unroll
    for (int ii = 0; ii < 8; ii++)
        dst[(size_t)(quad * 8 + ii) * Ee] = acc[ii];
}

// ---------------- M2 reduce + transpose + split (256 CTAs, MLP 8) ----------
__global__ __launch_bounds__(256) void m2t_reduce()
{
    const size_t stride = (size_t)Bb * 32 * Ee;
    int idx = blockIdx.x * 256 + threadIdx.x;     // 0..65535: [b][i][n]
    int b = idx >> 14;
    int i = (idx >> 9) & 31;
    int n = idx & 511;
    size_t po = ((size_t)b * 32 + i) * Ee + n;
    float p0 = g_M2p[0 * stride + po];
    float p1 = g_M2p[1 * stride + po];
    float p2 = g_M2p[2 * stride + po];
    float p3 = g_M2p[3 * stride + po];
    float p4 = g_M2p[4 * stride + po];
    float p5 = g_M2p[5 * stride + po];
    float p6 = g_M2p[6 * stride + po];
    float p7 = g_M2p[7 * stride + po];
    float s = ((p0 + p1) + (p2 + p3)) + ((p4 + p5) + (p6 + p7));
    __nv_bfloat16 h = __float2bfloat16(s);
    size_t off = ((size_t)b * Ee + n) * 32 + i;
    g_M2th[off] = h;
    g_M2tl[off] = __float2bfloat16(s - __bfloat162float(h));
}

// ---------------------------------------------------------------------------
extern "C" void kernel_launch(void* const* d_in, const int* in_sizes, int n_in,
                              void* d_out, int out_size)
{
    const float* x  = (const float*)d_in[0];
    const float* Wk = (const float*)d_in[1];
    const float* bk = (const float*)d_in[2];
    const float* Wq = (const float*)d_in[3];
    const float* bq = (const float*)d_in[4];
    const float* Wv = (const float*)d_in[5];
    const float* bv = (const float*)d_in[6];
    const float* Wu = (const float*)d_in[7];
    const float* bu = (const float*)d_in[8];
    float* out = (float*)d_out;

    float *pBias;
    __nv_bfloat16 *pxh, *pxl, *pWh, *pWl, *pUh, *pUl, *pch, *pcl, *pM2h, *pM2l;
    cudaGetSymbolAddress((void**)&pBias, g_bias);
    cudaGetSymbolAddress((void**)&pxh, g_xhi);
    cudaGetSymbolAddress((void**)&pxl, g_xlo);
    cudaGetSymbolAddress((void**)&pWh, g_Whi);
    cudaGetSymbolAddress((void**)&pWl, g_Wlo);
    cudaGetSymbolAddress((void**)&pUh, g_Uhi);
    cudaGetSymbolAddress((void**)&pUl, g_Ulo);
    cudaGetSymbolAddress((void**)&pch, g_chi);
    cudaGetSymbolAddress((void**)&pcl, g_clo);
    cudaGetSymbolAddress((void**)&pM2h, g_M2th);
    cudaGetSymbolAddress((void**)&pM2l, g_M2tl);

    cudaFuncSetAttribute(gemm_mma, cudaFuncAttributeMaxDynamicSharedMemorySize, GM_SMEM);
    cudaFuncSetAttribute(hs_h1_fused, cudaFuncAttributeMaxDynamicSharedMemorySize, HS_SMEM);

    // 1) fused prep
    prep_kernel<<<2048, 256>>>(x, Wk, Wq, Wv, Wu, bk, bq, bv);

    // 2) fused QKV projection -> split bf16 K|Q + fp32 V
    gemm_mma<<<dim3(NQKV / 128, MROWS / 128), 256, GM_SMEM>>>(
        pxh, pxl, pWh, pWl, nullptr, nullptr, pBias, nullptr, Ee, NQKV, 1);

    // 3-4) M2 chain
    m2t_part<<<dim3(Ee / 64, Bb, 8), 256>>>(Wu);
    m2t_reduce<<<256, 256>>>();

    // 5) fused scores + h1 output -> comb[0:544]
    hs_h1_fused<<<dim3(NBLK, Bb), 256, HS_SMEM>>>();

    // 6) out = comb @ [Wu1 | M2]^T + bu   (K = 544)
    gemm_mma<<<dim3(Ee / 128, MROWS / 128), 256, GM_SMEM>>>(
        pch, pcl, pUh, pUl, pM2h, pM2l, bu, out, COMB2, Ee, 0);
}